// round 4
// baseline (speedup 1.0000x reference)
#include <cuda_runtime.h>
#include <math.h>

// ---------------------------------------------------------------------------
// TransformerBlock: B=8, N=1024, C=768, H=12, Dh=64, MLP=3072, tokens M=8192
// Round 1 baseline: fp32 SIMT. 7 launches:
//   ln1 -> qkv gemm -> flash attn -> outproj(+bias+residual) -> ln2
//   -> mlp1(+bias+gelu) -> mlp2(+bias+residual)
// ---------------------------------------------------------------------------

#define M_TOK   8192
#define C_DIM   768
#define QKV_DIM 2304
#define MLP_DIM 3072
#define NHEAD   12
#define DH      64

// Scratch (allocation-free rule: __device__ globals)
__device__ float g_h[M_TOK * C_DIM];      // layernorm output
__device__ float g_qkv[M_TOK * QKV_DIM];  // qkv projection
__device__ float g_o[M_TOK * C_DIM];      // attention output
__device__ float g_mid[M_TOK * MLP_DIM];  // mlp hidden

// ---------------------------------------------------------------------------
// LayerNorm: one block per row (768 cols, 256 threads, 3 elems/thread)
// ---------------------------------------------------------------------------
__global__ __launch_bounds__(256) void ln_kernel(
    const float* __restrict__ x, const float* __restrict__ g,
    const float* __restrict__ b, float* __restrict__ out)
{
    int row = blockIdx.x;
    int tid = threadIdx.x;
    const float* xr = x + (size_t)row * C_DIM;

    float v0 = xr[tid];
    float v1 = xr[tid + 256];
    float v2 = xr[tid + 512];

    float s  = v0 + v1 + v2;
    float sq = v0 * v0 + v1 * v1 + v2 * v2;

    #pragma unroll
    for (int o = 16; o > 0; o >>= 1) {
        s  += __shfl_xor_sync(0xffffffffu, s,  o);
        sq += __shfl_xor_sync(0xffffffffu, sq, o);
    }

    __shared__ float ss[8], ssq[8];
    __shared__ float mu_s, rs_s;
    int w = tid >> 5;
    if ((tid & 31) == 0) { ss[w] = s; ssq[w] = sq; }
    __syncthreads();
    if (tid == 0) {
        float S = 0.f, SQ = 0.f;
        #pragma unroll
        for (int i = 0; i < 8; ++i) { S += ss[i]; SQ += ssq[i]; }
        float mu  = S * (1.0f / 768.0f);
        float var = SQ * (1.0f / 768.0f) - mu * mu;
        mu_s = mu;
        rs_s = rsqrtf(var + 1e-5f);
    }
    __syncthreads();
    float mu = mu_s, rs = rs_s;

    float* orow = out + (size_t)row * C_DIM;
    orow[tid]       = (v0 - mu) * rs * g[tid]       + b[tid];
    orow[tid + 256] = (v1 - mu) * rs * g[tid + 256] + b[tid + 256];
    orow[tid + 512] = (v2 - mu) * rs * g[tid + 512] + b[tid + 512];
}

// ---------------------------------------------------------------------------
// SGEMM: C[M,N] = A[M,K] @ B[K,N] (+bias) (+gelu) (+residual)
// 128x128 block tile, BK=8, 256 threads, 8x8 per thread.
// Requires M%128==0, N%128==0, K%8==0 (true for all calls here).
// ---------------------------------------------------------------------------
template <bool GELU>
__global__ __launch_bounds__(256) void sgemm_kernel(
    const float* __restrict__ A, const float* __restrict__ B,
    const float* __restrict__ bias, const float* __restrict__ R,
    float* __restrict__ C, int M, int N, int K)
{
    __shared__ __align__(16) float As[8][128];  // transposed: As[k][m]
    __shared__ __align__(16) float Bs[8][128];

    int tid = threadIdx.x;
    int bm = blockIdx.y << 7;
    int bn = blockIdx.x << 7;
    int tx = tid & 15;        // 0..15 -> 8 cols each
    int ty = tid >> 4;        // 0..15 -> 8 rows each

    int arow = tid >> 1;             // 0..127
    int acol = (tid & 1) << 2;       // 0 or 4
    int brow = tid >> 5;             // 0..7
    int bcol = (tid & 31) << 2;      // 0..124

    const float* Ap = A + (size_t)(bm + arow) * K + acol;
    const float* Bp = B + (size_t)brow * N + bn + bcol;

    float acc[8][8];
    #pragma unroll
    for (int i = 0; i < 8; ++i)
        #pragma unroll
        for (int j = 0; j < 8; ++j) acc[i][j] = 0.f;

    for (int k0 = 0; k0 < K; k0 += 8) {
        float4 av = *(const float4*)(Ap + k0);
        float4 bv = *(const float4*)(Bp + (size_t)k0 * N);

        As[acol + 0][arow] = av.x;
        As[acol + 1][arow] = av.y;
        As[acol + 2][arow] = av.z;
        As[acol + 3][arow] = av.w;
        *(float4*)&Bs[brow][bcol] = bv;
        __syncthreads();

        #pragma unroll
        for (int k = 0; k < 8; ++k) {
            float a[8], bb[8];
            *(float4*)&a[0]  = *(const float4*)&As[k][ty * 8];
            *(float4*)&a[4]  = *(const float4*)&As[k][ty * 8 + 4];
            *(float4*)&bb[0] = *(const float4*)&Bs[k][tx * 8];
            *(float4*)&bb[4] = *(const float4*)&Bs[k][tx * 8 + 4];
            #pragma unroll
            for (int i = 0; i < 8; ++i)
                #pragma unroll
                for (int j = 0; j < 8; ++j)
                    acc[i][j] += a[i] * bb[j];
        }
        __syncthreads();
    }

    // Epilogue
    #pragma unroll
    for (int i = 0; i < 8; ++i) {
        size_t row = (size_t)(bm + ty * 8 + i);
        float* Cp = C + row * N + bn + tx * 8;
        const float* Rp = R ? (R + row * N + bn + tx * 8) : nullptr;
        #pragma unroll
        for (int j = 0; j < 8; ++j) {
            float v = acc[i][j];
            if (bias) v += bias[bn + tx * 8 + j];
            if (GELU) v *= normcdff(v);   // exact gelu: x * Phi(x)
            if (Rp)   v += Rp[j];
            Cp[j] = v;
        }
    }
}

// ---------------------------------------------------------------------------
// Flash attention: one block per (b, h, 64-query tile).
// qkv layout per token row of 2304: [q(768) | k(768) | v(768)], head h at h*64.
// Output g_o layout: (b, n, h, d) -> token row of 768.
// ---------------------------------------------------------------------------
#define ATT_STRIDE 68
#define ATT_SMEM_FLOATS (4 * 64 * ATT_STRIDE + 128)

__global__ __launch_bounds__(256) void attn_kernel(
    const float* __restrict__ qkv, float* __restrict__ o)
{
    extern __shared__ float sm[];
    float* Qt   = sm;                         // [d][q]  d*68+q (pre-scaled)
    float* Kt   = sm + 64 * ATT_STRIDE;       // [d][kv]
    float* Vs   = sm + 2 * 64 * ATT_STRIDE;   // [kv][d]
    float* Ss   = sm + 3 * 64 * ATT_STRIDE;   // [q][kv]
    float* srow = sm + 4 * 64 * ATT_STRIDE;   // [64] rescale factors
    float* lrow = srow + 64;                  // [64] 1/l

    int b  = blockIdx.x / NHEAD;
    int h  = blockIdx.x % NHEAD;
    int q0 = blockIdx.y * 64;
    int tid = threadIdx.x;
    int tx = tid & 15;   // 4 cols each
    int ty = tid >> 4;   // 4 rows each

    const float* qbase = qkv + (size_t)b * 1024 * QKV_DIM + h * DH;

    // Load Q tile (scaled by 1/sqrt(Dh) = 0.125)
    for (int i = tid; i < 4096; i += 256) {
        int q = i >> 6, d = i & 63;
        Qt[d * ATT_STRIDE + q] = qbase[(size_t)(q0 + q) * QKV_DIM + d] * 0.125f;
    }

    float acc[4][4];
    #pragma unroll
    for (int i = 0; i < 4; ++i)
        #pragma unroll
        for (int c = 0; c < 4; ++c) acc[i][c] = 0.f;

    float mrow = -INFINITY, lsum = 0.f;  // valid for tid < 64 (row = tid)

    for (int j = 0; j < 16; ++j) {
        __syncthreads();  // Q load done (j=0); prev-iter Ss/Vs consumed (j>0)

        // Load K,V tiles for kv block j
        for (int i = tid; i < 4096; i += 256) {
            int kv = i >> 6, d = i & 63;
            size_t roff = (size_t)(j * 64 + kv) * QKV_DIM + d;
            Kt[d * ATT_STRIDE + kv] = qbase[roff + 768];
            Vs[kv * ATT_STRIDE + d] = qbase[roff + 1536];
        }
        __syncthreads();

        // S = Q K^T (pre-scaled): 4x4 micro-tile per thread
        float s[4][4];
        #pragma unroll
        for (int i = 0; i < 4; ++i)
            #pragma unroll
            for (int c = 0; c < 4; ++c) s[i][c] = 0.f;

        for (int d = 0; d < 64; ++d) {
            float4 qa = *(const float4*)&Qt[d * ATT_STRIDE + ty * 4];
            float4 ka = *(const float4*)&Kt[d * ATT_STRIDE + tx * 4];
            float qv[4] = {qa.x, qa.y, qa.z, qa.w};
            float kv4[4] = {ka.x, ka.y, ka.z, ka.w};
            #pragma unroll
            for (int i = 0; i < 4; ++i)
                #pragma unroll
                for (int c = 0; c < 4; ++c)
                    s[i][c] += qv[i] * kv4[c];
        }
        #pragma unroll
        for (int i = 0; i < 4; ++i)
            *(float4*)&Ss[(ty * 4 + i) * ATT_STRIDE + tx * 4] =
                make_float4(s[i][0], s[i][1], s[i][2], s[i][3]);
        __syncthreads();

        // Online softmax update (row r owned by thread r, r < 64)
        if (tid < 64) {
            float* srr = &Ss[tid * ATT_STRIDE];
            float mx = mrow;
            #pragma unroll 8
            for (int c = 0; c < 64; ++c) mx = fmaxf(mx, srr[c]);
            float scl = __expf(mrow - mx);
            float ls = 0.f;
            #pragma unroll 8
            for (int c = 0; c < 64; ++c) {
                float p = __expf(srr[c] - mx);
                srr[c] = p;
                ls += p;
            }
            lsum = lsum * scl + ls;
            mrow = mx;
            srow[tid] = scl;
        }
        __syncthreads();

        // O = O*scale + P @ V
        float scl4[4];
        #pragma unroll
        for (int i = 0; i < 4; ++i) scl4[i] = srow[ty * 4 + i];
        #pragma unroll
        for (int i = 0; i < 4; ++i)
            #pragma unroll
            for (int c = 0; c < 4; ++c) acc[i][c] *= scl4[i];

        for (int kv = 0; kv < 64; ++kv) {
            float4 v = *(const float4*)&Vs[kv * ATT_STRIDE + tx * 4];
            #pragma unroll
            for (int i = 0; i < 4; ++i) {
                float p = Ss[(ty * 4 + i) * ATT_STRIDE + kv];
                acc[i][0] += p * v.x;
                acc[i][1] += p * v.y;
                acc[i][2] += p * v.z;
                acc[i][3] += p * v.w;
            }
        }
    }

    __syncthreads();
    if (tid < 64) lrow[tid] = 1.0f / lsum;
    __syncthreads();

    #pragma unroll
    for (int i = 0; i < 4; ++i) {
        float inv = lrow[ty * 4 + i];
        size_t off = ((size_t)b * 1024 + q0 + ty * 4 + i) * C_DIM + h * DH + tx * 4;
        *(float4*)&o[off] = make_float4(acc[i][0] * inv, acc[i][1] * inv,
                                        acc[i][2] * inv, acc[i][3] * inv);
    }
}

// ---------------------------------------------------------------------------
// Launch
// ---------------------------------------------------------------------------
extern "C" void kernel_launch(void* const* d_in, const int* in_sizes, int n_in,
                              void* d_out, int out_size)
{
    const float* x     = (const float*)d_in[0];
    const float* ln1_g = (const float*)d_in[1];
    const float* ln1_b = (const float*)d_in[2];
    const float* w_qkv = (const float*)d_in[3];
    const float* w_out = (const float*)d_in[4];
    const float* b_out = (const float*)d_in[5];
    const float* ln2_g = (const float*)d_in[6];
    const float* ln2_b = (const float*)d_in[7];
    const float* w1    = (const float*)d_in[8];
    const float* b1    = (const float*)d_in[9];
    const float* w2    = (const float*)d_in[10];
    const float* b2    = (const float*)d_in[11];
    float* out = (float*)d_out;

    float *h, *qkv, *o, *mid;
    cudaGetSymbolAddress((void**)&h,   g_h);
    cudaGetSymbolAddress((void**)&qkv, g_qkv);
    cudaGetSymbolAddress((void**)&o,   g_o);
    cudaGetSymbolAddress((void**)&mid, g_mid);

    int attn_smem = ATT_SMEM_FLOATS * (int)sizeof(float);
    cudaFuncSetAttribute(attn_kernel, cudaFuncAttributeMaxDynamicSharedMemorySize,
                         attn_smem);

    // 1. h = LN1(x)
    ln_kernel<<<M_TOK, 256>>>(x, ln1_g, ln1_b, h);

    // 2. qkv = h @ w_qkv
    sgemm_kernel<false><<<dim3(QKV_DIM / 128, M_TOK / 128), 256>>>(
        h, w_qkv, nullptr, nullptr, qkv, M_TOK, QKV_DIM, C_DIM);

    // 3. o = attention(qkv)
    attn_kernel<<<dim3(8 * NHEAD, 1024 / 64), 256, attn_smem>>>(qkv, o);

    // 4. out = o @ w_out + b_out + x
    sgemm_kernel<false><<<dim3(C_DIM / 128, M_TOK / 128), 256>>>(
        o, w_out, b_out, x, out, M_TOK, C_DIM, C_DIM);

    // 5. h = LN2(out)
    ln_kernel<<<M_TOK, 256>>>(out, ln2_g, ln2_b, h);

    // 6. mid = gelu(h @ w1 + b1)
    sgemm_kernel<true><<<dim3(MLP_DIM / 128, M_TOK / 128), 256>>>(
        h, w1, b1, nullptr, mid, M_TOK, MLP_DIM, C_DIM);

    // 7. out = out + mid @ w2 + b2
    sgemm_kernel<false><<<dim3(C_DIM / 128, M_TOK / 128), 256>>>(
        mid, w2, b2, out, out, M_TOK, C_DIM, MLP_DIM);
}

// round 7
// speedup vs baseline: 2.4353x; 2.4353x over previous
#include <cuda_runtime.h>
#include <math.h>
#include <stdint.h>

// ---------------------------------------------------------------------------
// TransformerBlock: B=8, N=1024, C=768, H=12, Dh=64, MLP=3072, tokens M=8192
// Round 6: tcgen05 unavailable (harness targets plain sm_103) -> GEMMs via
// legacy warp-level mma.sync tf32 (m16n8k8), cp.async double-buffered.
// ---------------------------------------------------------------------------

#define M_TOK   8192
#define C_DIM   768
#define QKV_DIM 2304
#define MLP_DIM 3072
#define NHEAD   12
#define DH      64

// Scratch (allocation-free rule: __device__ globals)
__device__ float g_h[M_TOK * C_DIM];
__device__ float g_qkv[M_TOK * QKV_DIM];
__device__ float g_o[M_TOK * C_DIM];
__device__ float g_mid[M_TOK * MLP_DIM];
// Transposed weights (B operand of mma.row.col is [N,K] K-major)
__device__ float g_wqkv_t[QKV_DIM * C_DIM];
__device__ float g_wout_t[C_DIM * C_DIM];
__device__ float g_w1_t[MLP_DIM * C_DIM];
__device__ float g_w2_t[C_DIM * MLP_DIM];

// ---------------------------------------------------------------------------
// PTX helpers (sm_103-baseline only: cp.async + mma.sync)
// ---------------------------------------------------------------------------
__device__ __forceinline__ uint32_t smem_u32(const void* p) {
    uint32_t a;
    asm("{ .reg .u64 t; cvta.to.shared.u64 t, %1; cvt.u32.u64 %0, t; }"
        : "=r"(a) : "l"(p));
    return a;
}

__device__ __forceinline__ void cp_async16(uint32_t dst, const void* src) {
    asm volatile("cp.async.cg.shared.global [%0], [%1], 16;"
                 :: "r"(dst), "l"(src) : "memory");
}
#define CP_ASYNC_COMMIT() asm volatile("cp.async.commit_group;" ::: "memory")
#define CP_ASYNC_WAIT_1() asm volatile("cp.async.wait_group 1;" ::: "memory")

__device__ __forceinline__ uint32_t f2tf32(float f) {
    uint32_t r;
    asm("cvt.rna.tf32.f32 %0, %1;" : "=r"(r) : "f"(f));
    return r;
}

__device__ __forceinline__ void mma_tf32(float c[4], const uint32_t a[4],
                                         const uint32_t b[2]) {
    asm volatile(
        "mma.sync.aligned.m16n8k8.row.col.f32.tf32.tf32.f32 "
        "{%0,%1,%2,%3}, {%4,%5,%6,%7}, {%8,%9}, {%0,%1,%2,%3};"
        : "+f"(c[0]), "+f"(c[1]), "+f"(c[2]), "+f"(c[3])
        : "r"(a[0]), "r"(a[1]), "r"(a[2]), "r"(a[3]), "r"(b[0]), "r"(b[1]));
}

// ---------------------------------------------------------------------------
// Weight transpose: out[C][R] = in[R][C]
// ---------------------------------------------------------------------------
__global__ __launch_bounds__(256) void transpose_kernel(
    const float* __restrict__ in, float* __restrict__ out, int R, int C)
{
    __shared__ float t[32][33];
    int bx = blockIdx.x * 32;
    int by = blockIdx.y * 32;
    int x = threadIdx.x, y = threadIdx.y;  // 32 x 8
    #pragma unroll
    for (int i = 0; i < 32; i += 8)
        t[y + i][x] = in[(size_t)(by + y + i) * C + bx + x];
    __syncthreads();
    #pragma unroll
    for (int i = 0; i < 32; i += 8)
        out[(size_t)(bx + y + i) * R + by + x] = t[x][y + i];
}

// ---------------------------------------------------------------------------
// LayerNorm
// ---------------------------------------------------------------------------
__global__ __launch_bounds__(256) void ln_kernel(
    const float* __restrict__ x, const float* __restrict__ g,
    const float* __restrict__ b, float* __restrict__ out)
{
    int row = blockIdx.x;
    int tid = threadIdx.x;
    const float* xr = x + (size_t)row * C_DIM;

    float v0 = xr[tid];
    float v1 = xr[tid + 256];
    float v2 = xr[tid + 512];

    float s  = v0 + v1 + v2;
    float sq = v0 * v0 + v1 * v1 + v2 * v2;

    #pragma unroll
    for (int o = 16; o > 0; o >>= 1) {
        s  += __shfl_xor_sync(0xffffffffu, s,  o);
        sq += __shfl_xor_sync(0xffffffffu, sq, o);
    }

    __shared__ float ss[8], ssq[8];
    __shared__ float mu_s, rs_s;
    int w = tid >> 5;
    if ((tid & 31) == 0) { ss[w] = s; ssq[w] = sq; }
    __syncthreads();
    if (tid == 0) {
        float S = 0.f, SQ = 0.f;
        #pragma unroll
        for (int i = 0; i < 8; ++i) { S += ss[i]; SQ += ssq[i]; }
        float mu  = S * (1.0f / 768.0f);
        float var = SQ * (1.0f / 768.0f) - mu * mu;
        mu_s = mu;
        rs_s = rsqrtf(var + 1e-5f);
    }
    __syncthreads();
    float mu = mu_s, rs = rs_s;

    float* orow = out + (size_t)row * C_DIM;
    orow[tid]       = (v0 - mu) * rs * g[tid]       + b[tid];
    orow[tid + 256] = (v1 - mu) * rs * g[tid + 256] + b[tid + 256];
    orow[tid + 512] = (v2 - mu) * rs * g[tid + 512] + b[tid + 512];
}

// ---------------------------------------------------------------------------
// tf32 mma.sync GEMM: C[M,N] = A[M,K] @ Bt[N,K]^T (+bias) (+gelu) (+residual)
// CTA tile 128x128, BK=32, 8 warps (2x4), warp tile 64x32 (4x4 m16n8k8).
// SMEM per buffer: A 128x36 floats + B 128x36 floats (stride 36 -> fragment
// loads are bank-conflict-free). Double buffered cp.async pipeline.
// Requires M%128==0, N%128==0, K%32==0.
// ---------------------------------------------------------------------------
#define GS 36                     // smem row stride in floats
#define GEMM_BUF_FLOATS (2 * 128 * GS)   // A+B per buffer
#define GEMM_SMEM_BYTES (2 * GEMM_BUF_FLOATS * 4)

template <bool GELU>
__global__ __launch_bounds__(256, 2)
void mma_gemm_kernel(const float* __restrict__ A, const float* __restrict__ Bt,
                     const float* __restrict__ bias, const float* __restrict__ R,
                     float* __restrict__ C, int M, int N, int K)
{
    extern __shared__ float sm[];
    const uint32_t sm_addr = smem_u32(sm);

    const int tid = threadIdx.x;
    const int wid = tid >> 5;
    const int lane = tid & 31;
    const int tr = lane >> 2;      // 0..7
    const int tc = lane & 3;       // 0..3
    const int warp_m = wid >> 2;   // 0..1
    const int warp_n = wid & 3;    // 0..3
    const int bm = blockIdx.y << 7;
    const int bn = blockIdx.x << 7;

    // Loader mapping: 1024 float4 per tile, 4 per thread
    const int ld_row = tid >> 1;             // not used; flat mapping below
    (void)ld_row;

    float acc[4][4][4];
    #pragma unroll
    for (int mt = 0; mt < 4; ++mt)
        #pragma unroll
        for (int nt = 0; nt < 4; ++nt)
            #pragma unroll
            for (int q = 0; q < 4; ++q) acc[mt][nt][q] = 0.f;

    const int nc = K >> 5;

    // ---- async load of one K-chunk into buffer `buf` ----
    auto load_chunk = [&](int c, int buf) {
        uint32_t abase = sm_addr + buf * (GEMM_BUF_FLOATS * 4);
        uint32_t bbase = abase + 128 * GS * 4;
        const float* ag = A  + (size_t)bm * K + (size_t)(c << 5);
        const float* bg = Bt + (size_t)bn * K + (size_t)(c << 5);
        #pragma unroll
        for (int it = 0; it < 4; ++it) {
            int flat = tid + it * 256;       // 0..1023
            int row  = flat >> 3;            // 0..127
            int col4 = flat & 7;             // 0..7 (x4 floats)
            uint32_t soff = (uint32_t)(row * GS + col4 * 4) * 4;
            cp_async16(abase + soff, ag + (size_t)row * K + col4 * 4);
            cp_async16(bbase + soff, bg + (size_t)row * K + col4 * 4);
        }
        CP_ASYNC_COMMIT();
    };

    load_chunk(0, 0);

    for (int c = 0; c < nc; ++c) {
        if (c + 1 < nc) load_chunk(c + 1, (c + 1) & 1);
        else            CP_ASYNC_COMMIT();   // keep group count in lockstep
        CP_ASYNC_WAIT_1();                   // chunk c resident
        __syncthreads();

        const float* Asm = sm + (c & 1) * GEMM_BUF_FLOATS;
        const float* Bsm = Asm + 128 * GS;
        const float* a_ptr = Asm + (warp_m * 64 + tr) * GS + tc;
        const float* b_ptr = Bsm + (warp_n * 32 + tr) * GS + tc;

        #pragma unroll
        for (int ks = 0; ks < 4; ++ks) {
            uint32_t af[4][4], bf[4][2];
            #pragma unroll
            for (int mt = 0; mt < 4; ++mt) {
                const float* p = a_ptr + mt * 16 * GS + ks * 8;
                af[mt][0] = f2tf32(p[0]);
                af[mt][1] = f2tf32(p[8 * GS]);
                af[mt][2] = f2tf32(p[4]);
                af[mt][3] = f2tf32(p[8 * GS + 4]);
            }
            #pragma unroll
            for (int nt = 0; nt < 4; ++nt) {
                const float* p = b_ptr + nt * 8 * GS + ks * 8;
                bf[nt][0] = f2tf32(p[0]);
                bf[nt][1] = f2tf32(p[4]);
            }
            #pragma unroll
            for (int mt = 0; mt < 4; ++mt)
                #pragma unroll
                for (int nt = 0; nt < 4; ++nt)
                    mma_tf32(acc[mt][nt], af[mt], bf[nt]);
        }
        __syncthreads();
    }

    // ---- epilogue ----
    const int row0 = bm + warp_m * 64 + tr;
    const int col0 = bn + warp_n * 32 + tc * 2;

    // bias pairs per n-tile
    float2 bp[4];
    #pragma unroll
    for (int nt = 0; nt < 4; ++nt) {
        if (bias) {
            bp[nt].x = __ldg(&bias[col0 + nt * 8]);
            bp[nt].y = __ldg(&bias[col0 + nt * 8 + 1]);
        } else {
            bp[nt].x = 0.f; bp[nt].y = 0.f;
        }
    }

    #pragma unroll
    for (int mt = 0; mt < 4; ++mt) {
        #pragma unroll
        for (int half = 0; half < 2; ++half) {
            int r = row0 + mt * 16 + half * 8;
            float* Cp = C + (size_t)r * N;
            const float* Rp = R ? (R + (size_t)r * N) : nullptr;
            #pragma unroll
            for (int nt = 0; nt < 4; ++nt) {
                int cl = col0 + nt * 8;
                float v0 = acc[mt][nt][half * 2 + 0] + bp[nt].x;
                float v1 = acc[mt][nt][half * 2 + 1] + bp[nt].y;
                if (GELU) { v0 *= normcdff(v0); v1 *= normcdff(v1); }
                if (Rp) {
                    float2 rv = *(const float2*)(Rp + cl);
                    v0 += rv.x; v1 += rv.y;
                }
                *(float2*)(Cp + cl) = make_float2(v0, v1);
            }
        }
    }
}

// ---------------------------------------------------------------------------
// Flash attention (SIMT, unchanged)
// ---------------------------------------------------------------------------
#define ATT_STRIDE 68
#define ATT_SMEM_FLOATS (4 * 64 * ATT_STRIDE + 128)

__global__ __launch_bounds__(256) void attn_kernel(
    const float* __restrict__ qkv, float* __restrict__ o)
{
    extern __shared__ float sm[];
    float* Qt   = sm;
    float* Kt   = sm + 64 * ATT_STRIDE;
    float* Vs   = sm + 2 * 64 * ATT_STRIDE;
    float* Ss   = sm + 3 * 64 * ATT_STRIDE;
    float* srow = sm + 4 * 64 * ATT_STRIDE;
    float* lrow = srow + 64;

    int b  = blockIdx.x / NHEAD;
    int h  = blockIdx.x % NHEAD;
    int q0 = blockIdx.y * 64;
    int tid = threadIdx.x;
    int tx = tid & 15;
    int ty = tid >> 4;

    const float* qbase = qkv + (size_t)b * 1024 * QKV_DIM + h * DH;

    for (int i = tid; i < 4096; i += 256) {
        int q = i >> 6, d = i & 63;
        Qt[d * ATT_STRIDE + q] = qbase[(size_t)(q0 + q) * QKV_DIM + d] * 0.125f;
    }

    float acc[4][4];
    #pragma unroll
    for (int i = 0; i < 4; ++i)
        #pragma unroll
        for (int c = 0; c < 4; ++c) acc[i][c] = 0.f;

    float mrow = -INFINITY, lsum = 0.f;

    for (int j = 0; j < 16; ++j) {
        __syncthreads();

        for (int i = tid; i < 4096; i += 256) {
            int kv = i >> 6, d = i & 63;
            size_t roff = (size_t)(j * 64 + kv) * QKV_DIM + d;
            Kt[d * ATT_STRIDE + kv] = qbase[roff + 768];
            Vs[kv * ATT_STRIDE + d] = qbase[roff + 1536];
        }
        __syncthreads();

        float s[4][4];
        #pragma unroll
        for (int i = 0; i < 4; ++i)
            #pragma unroll
            for (int c = 0; c < 4; ++c) s[i][c] = 0.f;

        for (int d = 0; d < 64; ++d) {
            float4 qa = *(const float4*)&Qt[d * ATT_STRIDE + ty * 4];
            float4 ka = *(const float4*)&Kt[d * ATT_STRIDE + tx * 4];
            float qv[4] = {qa.x, qa.y, qa.z, qa.w};
            float kv4[4] = {ka.x, ka.y, ka.z, ka.w};
            #pragma unroll
            for (int i = 0; i < 4; ++i)
                #pragma unroll
                for (int c = 0; c < 4; ++c)
                    s[i][c] += qv[i] * kv4[c];
        }
        #pragma unroll
        for (int i = 0; i < 4; ++i)
            *(float4*)&Ss[(ty * 4 + i) * ATT_STRIDE + tx * 4] =
                make_float4(s[i][0], s[i][1], s[i][2], s[i][3]);
        __syncthreads();

        if (tid < 64) {
            float* srr = &Ss[tid * ATT_STRIDE];
            float mx = mrow;
            #pragma unroll 8
            for (int c = 0; c < 64; ++c) mx = fmaxf(mx, srr[c]);
            float scl = __expf(mrow - mx);
            float ls = 0.f;
            #pragma unroll 8
            for (int c = 0; c < 64; ++c) {
                float p = __expf(srr[c] - mx);
                srr[c] = p;
                ls += p;
            }
            lsum = lsum * scl + ls;
            mrow = mx;
            srow[tid] = scl;
        }
        __syncthreads();

        float scl4[4];
        #pragma unroll
        for (int i = 0; i < 4; ++i) scl4[i] = srow[ty * 4 + i];
        #pragma unroll
        for (int i = 0; i < 4; ++i)
            #pragma unroll
            for (int c = 0; c < 4; ++c) acc[i][c] *= scl4[i];

        for (int kv = 0; kv < 64; ++kv) {
            float4 v = *(const float4*)&Vs[kv * ATT_STRIDE + tx * 4];
            #pragma unroll
            for (int i = 0; i < 4; ++i) {
                float p = Ss[(ty * 4 + i) * ATT_STRIDE + kv];
                acc[i][0] += p * v.x;
                acc[i][1] += p * v.y;
                acc[i][2] += p * v.z;
                acc[i][3] += p * v.w;
            }
        }
    }

    __syncthreads();
    if (tid < 64) lrow[tid] = 1.0f / lsum;
    __syncthreads();

    #pragma unroll
    for (int i = 0; i < 4; ++i) {
        float inv = lrow[ty * 4 + i];
        size_t off = ((size_t)b * 1024 + q0 + ty * 4 + i) * C_DIM + h * DH + tx * 4;
        *(float4*)&o[off] = make_float4(acc[i][0] * inv, acc[i][1] * inv,
                                        acc[i][2] * inv, acc[i][3] * inv);
    }
}

// ---------------------------------------------------------------------------
// Launch
// ---------------------------------------------------------------------------
extern "C" void kernel_launch(void* const* d_in, const int* in_sizes, int n_in,
                              void* d_out, int out_size)
{
    const float* x     = (const float*)d_in[0];
    const float* ln1_g = (const float*)d_in[1];
    const float* ln1_b = (const float*)d_in[2];
    const float* w_qkv = (const float*)d_in[3];
    const float* w_out = (const float*)d_in[4];
    const float* b_out = (const float*)d_in[5];
    const float* ln2_g = (const float*)d_in[6];
    const float* ln2_b = (const float*)d_in[7];
    const float* w1    = (const float*)d_in[8];
    const float* b1    = (const float*)d_in[9];
    const float* w2    = (const float*)d_in[10];
    const float* b2    = (const float*)d_in[11];
    float* out = (float*)d_out;

    float *h, *qkv, *o, *mid, *wqkv_t, *wout_t, *w1_t, *w2_t;
    cudaGetSymbolAddress((void**)&h,      g_h);
    cudaGetSymbolAddress((void**)&qkv,    g_qkv);
    cudaGetSymbolAddress((void**)&o,      g_o);
    cudaGetSymbolAddress((void**)&mid,    g_mid);
    cudaGetSymbolAddress((void**)&wqkv_t, g_wqkv_t);
    cudaGetSymbolAddress((void**)&wout_t, g_wout_t);
    cudaGetSymbolAddress((void**)&w1_t,   g_w1_t);
    cudaGetSymbolAddress((void**)&w2_t,   g_w2_t);

    int attn_smem = ATT_SMEM_FLOATS * (int)sizeof(float);
    cudaFuncSetAttribute(attn_kernel, cudaFuncAttributeMaxDynamicSharedMemorySize,
                         attn_smem);
    cudaFuncSetAttribute(mma_gemm_kernel<false>,
                         cudaFuncAttributeMaxDynamicSharedMemorySize, GEMM_SMEM_BYTES);
    cudaFuncSetAttribute(mma_gemm_kernel<true>,
                         cudaFuncAttributeMaxDynamicSharedMemorySize, GEMM_SMEM_BYTES);

    dim3 tb(32, 8);
    // 0. Transpose weights to [N,K]
    transpose_kernel<<<dim3(QKV_DIM / 32, C_DIM / 32), tb>>>(w_qkv, wqkv_t, C_DIM, QKV_DIM);
    transpose_kernel<<<dim3(C_DIM / 32, C_DIM / 32),   tb>>>(w_out, wout_t, C_DIM, C_DIM);
    transpose_kernel<<<dim3(MLP_DIM / 32, C_DIM / 32), tb>>>(w1, w1_t, C_DIM, MLP_DIM);
    transpose_kernel<<<dim3(C_DIM / 32, MLP_DIM / 32), tb>>>(w2, w2_t, MLP_DIM, C_DIM);

    // 1. h = LN1(x)
    ln_kernel<<<M_TOK, 256>>>(x, ln1_g, ln1_b, h);

    // 2. qkv = h @ w_qkv
    mma_gemm_kernel<false><<<dim3(QKV_DIM / 128, M_TOK / 128), 256, GEMM_SMEM_BYTES>>>(
        h, wqkv_t, nullptr, nullptr, qkv, M_TOK, QKV_DIM, C_DIM);

    // 3. o = attention(qkv)
    attn_kernel<<<dim3(8 * NHEAD, 1024 / 64), 256, attn_smem>>>(qkv, o);

    // 4. out = o @ w_out + b_out + x
    mma_gemm_kernel<false><<<dim3(C_DIM / 128, M_TOK / 128), 256, GEMM_SMEM_BYTES>>>(
        o, wout_t, b_out, x, out, M_TOK, C_DIM, C_DIM);

    // 5. h = LN2(out)
    ln_kernel<<<M_TOK, 256>>>(out, ln2_g, ln2_b, h);

    // 6. mid = gelu(h @ w1 + b1)
    mma_gemm_kernel<true><<<dim3(MLP_DIM / 128, M_TOK / 128), 256, GEMM_SMEM_BYTES>>>(
        h, w1_t, b1, nullptr, mid, M_TOK, MLP_DIM, C_DIM);

    // 7. out = out + mid @ w2 + b2
    mma_gemm_kernel<false><<<dim3(C_DIM / 128, M_TOK / 128), 256, GEMM_SMEM_BYTES>>>(
        mid, w2_t, b2, out, out, M_TOK, C_DIM, MLP_DIM);
}

// round 8
// speedup vs baseline: 3.3368x; 1.3702x over previous
#include <cuda_runtime.h>
#include <math.h>
#include <stdint.h>

// ---------------------------------------------------------------------------
// TransformerBlock: B=8, N=1024, C=768, H=12, Dh=64, MLP=3072, tokens M=8192
// Round 8: producer-side tf32 rounding (no CVT in GEMM hot loop) +
//          mma.sync-based flash attention.
// ---------------------------------------------------------------------------

#define M_TOK   8192
#define C_DIM   768
#define QKV_DIM 2304
#define MLP_DIM 3072
#define NHEAD   12
#define DH      64

// Scratch (allocation-free rule: __device__ globals)
__device__ float g_h[M_TOK * C_DIM];
__device__ float g_qkv[M_TOK * QKV_DIM];
__device__ float g_o[M_TOK * C_DIM];
__device__ float g_mid[M_TOK * MLP_DIM];
__device__ float g_wqkv_t[QKV_DIM * C_DIM];
__device__ float g_wout_t[C_DIM * C_DIM];
__device__ float g_w1_t[MLP_DIM * C_DIM];
__device__ float g_w2_t[C_DIM * MLP_DIM];

// ---------------------------------------------------------------------------
// PTX helpers
// ---------------------------------------------------------------------------
__device__ __forceinline__ uint32_t smem_u32(const void* p) {
    uint32_t a;
    asm("{ .reg .u64 t; cvta.to.shared.u64 t, %1; cvt.u32.u64 %0, t; }"
        : "=r"(a) : "l"(p));
    return a;
}

__device__ __forceinline__ void cp_async16(uint32_t dst, const void* src) {
    asm volatile("cp.async.cg.shared.global [%0], [%1], 16;"
                 :: "r"(dst), "l"(src) : "memory");
}
#define CP_ASYNC_COMMIT() asm volatile("cp.async.commit_group;" ::: "memory")
#define CP_ASYNC_WAIT_1() asm volatile("cp.async.wait_group 1;" ::: "memory")
#define CP_ASYNC_WAIT_0() asm volatile("cp.async.wait_group 0;" ::: "memory")

// round-to-nearest tf32, returned as a valid float bit pattern
__device__ __forceinline__ float rnd_tf32(float f) {
    uint32_t u;
    asm("cvt.rna.tf32.f32 %0, %1;" : "=r"(u) : "f"(f));
    return __uint_as_float(u);
}

__device__ __forceinline__ void mma_tf32(float c[4], const uint32_t a[4],
                                         const uint32_t b[2]) {
    asm volatile(
        "mma.sync.aligned.m16n8k8.row.col.f32.tf32.tf32.f32 "
        "{%0,%1,%2,%3}, {%4,%5,%6,%7}, {%8,%9}, {%0,%1,%2,%3};"
        : "+f"(c[0]), "+f"(c[1]), "+f"(c[2]), "+f"(c[3])
        : "r"(a[0]), "r"(a[1]), "r"(a[2]), "r"(a[3]), "r"(b[0]), "r"(b[1]));
}

// ---------------------------------------------------------------------------
// Weight transpose: out[C][R] = tf32(in[R][C])
// ---------------------------------------------------------------------------
__global__ __launch_bounds__(256) void transpose_kernel(
    const float* __restrict__ in, float* __restrict__ out, int R, int C)
{
    __shared__ float t[32][33];
    int bx = blockIdx.x * 32;
    int by = blockIdx.y * 32;
    int x = threadIdx.x, y = threadIdx.y;  // 32 x 8
    #pragma unroll
    for (int i = 0; i < 32; i += 8)
        t[y + i][x] = in[(size_t)(by + y + i) * C + bx + x];
    __syncthreads();
    #pragma unroll
    for (int i = 0; i < 32; i += 8)
        out[(size_t)(bx + y + i) * R + by + x] = rnd_tf32(t[x][y + i]);
}

// ---------------------------------------------------------------------------
// LayerNorm (output tf32-rounded: feeds MMA A operands only)
// ---------------------------------------------------------------------------
__global__ __launch_bounds__(256) void ln_kernel(
    const float* __restrict__ x, const float* __restrict__ g,
    const float* __restrict__ b, float* __restrict__ out)
{
    int row = blockIdx.x;
    int tid = threadIdx.x;
    const float* xr = x + (size_t)row * C_DIM;

    float v0 = xr[tid];
    float v1 = xr[tid + 256];
    float v2 = xr[tid + 512];

    float s  = v0 + v1 + v2;
    float sq = v0 * v0 + v1 * v1 + v2 * v2;

    #pragma unroll
    for (int o = 16; o > 0; o >>= 1) {
        s  += __shfl_xor_sync(0xffffffffu, s,  o);
        sq += __shfl_xor_sync(0xffffffffu, sq, o);
    }

    __shared__ float ss[8], ssq[8];
    __shared__ float mu_s, rs_s;
    int w = tid >> 5;
    if ((tid & 31) == 0) { ss[w] = s; ssq[w] = sq; }
    __syncthreads();
    if (tid == 0) {
        float S = 0.f, SQ = 0.f;
        #pragma unroll
        for (int i = 0; i < 8; ++i) { S += ss[i]; SQ += ssq[i]; }
        float mu  = S * (1.0f / 768.0f);
        float var = SQ * (1.0f / 768.0f) - mu * mu;
        mu_s = mu;
        rs_s = rsqrtf(var + 1e-5f);
    }
    __syncthreads();
    float mu = mu_s, rs = rs_s;

    float* orow = out + (size_t)row * C_DIM;
    orow[tid]       = rnd_tf32((v0 - mu) * rs * g[tid]       + b[tid]);
    orow[tid + 256] = rnd_tf32((v1 - mu) * rs * g[tid + 256] + b[tid + 256]);
    orow[tid + 512] = rnd_tf32((v2 - mu) * rs * g[tid + 512] + b[tid + 512]);
}

// ---------------------------------------------------------------------------
// tf32 mma.sync GEMM: C[M,N] = A[M,K] @ Bt[N,K]^T (+bias) (+gelu) (+residual)
// A and Bt MUST be pre-rounded to tf32 by their producers.
// CTA 128x128, BK=32, 8 warps (2x4), warp tile 64x32. Double-buffered cp.async.
// ---------------------------------------------------------------------------
#define GS 36
#define GEMM_BUF_FLOATS (2 * 128 * GS)
#define GEMM_SMEM_BYTES (2 * GEMM_BUF_FLOATS * 4)

template <bool GELU, bool ROUND>
__global__ __launch_bounds__(256, 2)
void mma_gemm_kernel(const float* __restrict__ A, const float* __restrict__ Bt,
                     const float* __restrict__ bias, const float* __restrict__ R,
                     float* __restrict__ C, int M, int N, int K)
{
    extern __shared__ float sm[];
    const uint32_t sm_addr = smem_u32(sm);

    const int tid = threadIdx.x;
    const int wid = tid >> 5;
    const int lane = tid & 31;
    const int tr = lane >> 2;
    const int tc = lane & 3;
    const int warp_m = wid >> 2;
    const int warp_n = wid & 3;
    const int bm = blockIdx.y << 7;
    const int bn = blockIdx.x << 7;

    float acc[4][4][4];
    #pragma unroll
    for (int mt = 0; mt < 4; ++mt)
        #pragma unroll
        for (int nt = 0; nt < 4; ++nt)
            #pragma unroll
            for (int q = 0; q < 4; ++q) acc[mt][nt][q] = 0.f;

    const int nc = K >> 5;

    auto load_chunk = [&](int c, int buf) {
        uint32_t abase = sm_addr + buf * (GEMM_BUF_FLOATS * 4);
        uint32_t bbase = abase + 128 * GS * 4;
        const float* ag = A  + (size_t)bm * K + (size_t)(c << 5);
        const float* bg = Bt + (size_t)bn * K + (size_t)(c << 5);
        #pragma unroll
        for (int it = 0; it < 4; ++it) {
            int flat = tid + it * 256;
            int row  = flat >> 3;
            int col4 = flat & 7;
            uint32_t soff = (uint32_t)(row * GS + col4 * 4) * 4;
            cp_async16(abase + soff, ag + (size_t)row * K + col4 * 4);
            cp_async16(bbase + soff, bg + (size_t)row * K + col4 * 4);
        }
        CP_ASYNC_COMMIT();
    };

    load_chunk(0, 0);

    for (int c = 0; c < nc; ++c) {
        if (c + 1 < nc) load_chunk(c + 1, (c + 1) & 1);
        else            CP_ASYNC_COMMIT();
        CP_ASYNC_WAIT_1();
        __syncthreads();

        const float* Asm = sm + (c & 1) * GEMM_BUF_FLOATS;
        const float* Bsm = Asm + 128 * GS;
        const float* a_ptr = Asm + (warp_m * 64 + tr) * GS + tc;
        const float* b_ptr = Bsm + (warp_n * 32 + tr) * GS + tc;

        #pragma unroll
        for (int ks = 0; ks < 4; ++ks) {
            uint32_t af[4][4], bf[4][2];
            #pragma unroll
            for (int mt = 0; mt < 4; ++mt) {
                const float* p = a_ptr + mt * 16 * GS + ks * 8;
                af[mt][0] = __float_as_uint(p[0]);
                af[mt][1] = __float_as_uint(p[8 * GS]);
                af[mt][2] = __float_as_uint(p[4]);
                af[mt][3] = __float_as_uint(p[8 * GS + 4]);
            }
            #pragma unroll
            for (int nt = 0; nt < 4; ++nt) {
                const float* p = b_ptr + nt * 8 * GS + ks * 8;
                bf[nt][0] = __float_as_uint(p[0]);
                bf[nt][1] = __float_as_uint(p[4]);
            }
            #pragma unroll
            for (int mt = 0; mt < 4; ++mt)
                #pragma unroll
                for (int nt = 0; nt < 4; ++nt)
                    mma_tf32(acc[mt][nt], af[mt], bf[nt]);
        }
        __syncthreads();
    }

    const int row0 = bm + warp_m * 64 + tr;
    const int col0 = bn + warp_n * 32 + tc * 2;

    float2 bp[4];
    #pragma unroll
    for (int nt = 0; nt < 4; ++nt) {
        if (bias) {
            bp[nt].x = __ldg(&bias[col0 + nt * 8]);
            bp[nt].y = __ldg(&bias[col0 + nt * 8 + 1]);
        } else {
            bp[nt].x = 0.f; bp[nt].y = 0.f;
        }
    }

    #pragma unroll
    for (int mt = 0; mt < 4; ++mt) {
        #pragma unroll
        for (int half = 0; half < 2; ++half) {
            int r = row0 + mt * 16 + half * 8;
            float* Cp = C + (size_t)r * N;
            const float* Rp = R ? (R + (size_t)r * N) : nullptr;
            #pragma unroll
            for (int nt = 0; nt < 4; ++nt) {
                int cl = col0 + nt * 8;
                float v0 = acc[mt][nt][half * 2 + 0] + bp[nt].x;
                float v1 = acc[mt][nt][half * 2 + 1] + bp[nt].y;
                if (GELU) { v0 *= normcdff(v0); v1 *= normcdff(v1); }
                if (Rp) {
                    float2 rv = *(const float2*)(Rp + cl);
                    v0 += rv.x; v1 += rv.y;
                }
                if (ROUND) { v0 = rnd_tf32(v0); v1 = rnd_tf32(v1); }
                *(float2*)(Cp + cl) = make_float2(v0, v1);
            }
        }
    }
}

// ---------------------------------------------------------------------------
// Flash attention via mma.sync: CTA = (b, h, 128-query tile), 256 threads.
// qkv must be tf32-pre-rounded. Output o is tf32-rounded (feeds out-proj).
// smem: Q[128][68], K[128][68], V[128][68], S[128][132], srow[128]
// ---------------------------------------------------------------------------
#define QS   68
#define SSTR 132
#define ATT_SMEM_BYTES ((3 * 128 * QS + 128 * SSTR + 128) * 4)

__global__ __launch_bounds__(256, 1) void attn_mma_kernel(
    const float* __restrict__ qkv, float* __restrict__ o)
{
    extern __shared__ float sm[];
    float* Qs   = sm;
    float* Ks   = Qs + 128 * QS;
    float* Vs   = Ks + 128 * QS;
    float* Ss   = Vs + 128 * QS;
    float* srow = Ss + 128 * SSTR;

    const uint32_t Qs_a = smem_u32(Qs);
    const uint32_t Ks_a = smem_u32(Ks);
    const uint32_t Vs_a = smem_u32(Vs);

    const int b = blockIdx.x / NHEAD;
    const int h = blockIdx.x % NHEAD;
    const int q0 = blockIdx.y << 7;
    const int tid = threadIdx.x;
    const int wid = tid >> 5, lane = tid & 31;
    const int tr = lane >> 2, tc = lane & 3;
    const int warp_m = wid >> 2;   // 0..1
    const int warp_n = wid & 3;    // 0..3

    const float* base = qkv + (size_t)b * 1024 * QKV_DIM + h * DH;

    // Q tile load (raw; softmax folds the 1/8 scale)
    {
        const int row = tid >> 1, half = tid & 1;
        const float* src = base + (size_t)(q0 + row) * QKV_DIM + half * 32;
        uint32_t dst = Qs_a + (uint32_t)(row * QS + half * 32) * 4;
        #pragma unroll
        for (int i = 0; i < 8; ++i) cp_async16(dst + i * 16, src + i * 4);
        CP_ASYNC_COMMIT();
    }

    float oacc[4][2][4];
    #pragma unroll
    for (int mt = 0; mt < 4; ++mt)
        #pragma unroll
        for (int nt = 0; nt < 2; ++nt)
            #pragma unroll
            for (int q = 0; q < 4; ++q) oacc[mt][nt][q] = 0.f;

    float m_run = -INFINITY, l_run = 0.f;   // row state, owner thread tid<128

    for (int kc = 0; kc < 8; ++kc) {
        __syncthreads();   // prev iter's PV reads of Ks/Vs complete

        // K chunk (group), then V chunk (group)
        {
            const int row = tid >> 1, half = tid & 1;
            const float* ksrc = base + (size_t)(kc * 128 + row) * QKV_DIM + 768 + half * 32;
            uint32_t kdst = Ks_a + (uint32_t)(row * QS + half * 32) * 4;
            #pragma unroll
            for (int i = 0; i < 8; ++i) cp_async16(kdst + i * 16, ksrc + i * 4);
            CP_ASYNC_COMMIT();
            const float* vsrc = ksrc + 768;
            uint32_t vdst = Vs_a + (uint32_t)(row * QS + half * 32) * 4;
            #pragma unroll
            for (int i = 0; i < 8; ++i) cp_async16(vdst + i * 16, vsrc + i * 4);
            CP_ASYNC_COMMIT();
        }
        CP_ASYNC_WAIT_1();     // Q (+prev) and K resident; V may be in flight
        __syncthreads();

        // ---- S = Q @ K^T (warp tile 64x32) ----
        float sacc[4][4][4];
        #pragma unroll
        for (int mt = 0; mt < 4; ++mt)
            #pragma unroll
            for (int nt = 0; nt < 4; ++nt)
                #pragma unroll
                for (int q = 0; q < 4; ++q) sacc[mt][nt][q] = 0.f;

        const float* a_base = Qs + (warp_m * 64 + tr) * QS + tc;
        const float* b_base = Ks + (warp_n * 32 + tr) * QS + tc;
        #pragma unroll
        for (int ksi = 0; ksi < 8; ++ksi) {
            uint32_t af[4][4], bf[4][2];
            #pragma unroll
            for (int mt = 0; mt < 4; ++mt) {
                const float* p = a_base + mt * 16 * QS + ksi * 8;
                af[mt][0] = __float_as_uint(p[0]);
                af[mt][1] = __float_as_uint(p[8 * QS]);
                af[mt][2] = __float_as_uint(p[4]);
                af[mt][3] = __float_as_uint(p[8 * QS + 4]);
            }
            #pragma unroll
            for (int nt = 0; nt < 4; ++nt) {
                const float* p = b_base + nt * 8 * QS + ksi * 8;
                bf[nt][0] = __float_as_uint(p[0]);
                bf[nt][1] = __float_as_uint(p[4]);
            }
            #pragma unroll
            for (int mt = 0; mt < 4; ++mt)
                #pragma unroll
                for (int nt = 0; nt < 4; ++nt)
                    mma_tf32(sacc[mt][nt], af[mt], bf[nt]);
        }
        // store S tile
        #pragma unroll
        for (int mt = 0; mt < 4; ++mt) {
            int r0 = warp_m * 64 + mt * 16 + tr;
            #pragma unroll
            for (int nt = 0; nt < 4; ++nt) {
                int c0 = warp_n * 32 + nt * 8 + tc * 2;
                *(float2*)&Ss[r0 * SSTR + c0] =
                    make_float2(sacc[mt][nt][0], sacc[mt][nt][1]);
                *(float2*)&Ss[(r0 + 8) * SSTR + c0] =
                    make_float2(sacc[mt][nt][2], sacc[mt][nt][3]);
            }
        }
        __syncthreads();

        // ---- online softmax, row r = tid (tid < 128) ----
        if (tid < 128) {
            float* srr = &Ss[tid * SSTR];
            float mx = -INFINITY;
            #pragma unroll 8
            for (int c4 = 0; c4 < 32; ++c4) {
                float4 v = *(const float4*)&srr[c4 * 4];
                mx = fmaxf(mx, fmaxf(fmaxf(v.x, v.y), fmaxf(v.z, v.w)));
            }
            float m_new = fmaxf(m_run, 0.125f * mx);
            float scl = __expf(m_run - m_new);
            float ls = 0.f;
            #pragma unroll 8
            for (int c4 = 0; c4 < 32; ++c4) {
                float4 v = *(const float4*)&srr[c4 * 4];
                v.x = rnd_tf32(__expf(fmaf(0.125f, v.x, -m_new)));
                v.y = rnd_tf32(__expf(fmaf(0.125f, v.y, -m_new)));
                v.z = rnd_tf32(__expf(fmaf(0.125f, v.z, -m_new)));
                v.w = rnd_tf32(__expf(fmaf(0.125f, v.w, -m_new)));
                ls += v.x + v.y + v.z + v.w;   // sum of rounded p: consistent
                *(float4*)&srr[c4 * 4] = v;
            }
            l_run = l_run * scl + ls;
            m_run = m_new;
            srow[tid] = scl;
        }
        CP_ASYNC_WAIT_0();     // V resident
        __syncthreads();       // P, srow, V visible to all

        // ---- O = O*scl + P @ V (warp tile 64x16 of O) ----
        #pragma unroll
        for (int mt = 0; mt < 4; ++mt) {
            float s0 = srow[warp_m * 64 + mt * 16 + tr];
            float s1 = srow[warp_m * 64 + mt * 16 + tr + 8];
            #pragma unroll
            for (int nt = 0; nt < 2; ++nt) {
                oacc[mt][nt][0] *= s0; oacc[mt][nt][1] *= s0;
                oacc[mt][nt][2] *= s1; oacc[mt][nt][3] *= s1;
            }
        }
        const float* pa_base = Ss + (warp_m * 64 + tr) * SSTR + tc;
        const float* vb_base = Vs + tc * QS + warp_n * 16 + tr;
        #pragma unroll
        for (int ksi = 0; ksi < 16; ++ksi) {
            uint32_t af[4][4], bf[2][2];
            #pragma unroll
            for (int mt = 0; mt < 4; ++mt) {
                const float* p = pa_base + mt * 16 * SSTR + ksi * 8;
                af[mt][0] = __float_as_uint(p[0]);
                af[mt][1] = __float_as_uint(p[8 * SSTR]);
                af[mt][2] = __float_as_uint(p[4]);
                af[mt][3] = __float_as_uint(p[8 * SSTR + 4]);
            }
            #pragma unroll
            for (int nt = 0; nt < 2; ++nt) {
                const float* p = vb_base + ksi * 8 * QS + nt * 8;
                bf[nt][0] = __float_as_uint(p[0]);
                bf[nt][1] = __float_as_uint(p[4 * QS]);
            }
            #pragma unroll
            for (int mt = 0; mt < 4; ++mt)
                #pragma unroll
                for (int nt = 0; nt < 2; ++nt)
                    mma_tf32(oacc[mt][nt], af[mt], bf[nt]);
        }
    }

    __syncthreads();
    if (tid < 128) srow[tid] = 1.0f / l_run;
    __syncthreads();

    // epilogue: o[token][h*64 + d], tf32-rounded (feeds out-proj MMA)
    #pragma unroll
    for (int mt = 0; mt < 4; ++mt) {
        int r0 = warp_m * 64 + mt * 16 + tr;
        float i0 = srow[r0], i1 = srow[r0 + 8];
        size_t g0 = ((size_t)b * 1024 + q0 + r0) * C_DIM + h * DH
                    + warp_n * 16 + tc * 2;
        size_t g1 = g0 + (size_t)8 * C_DIM;
        #pragma unroll
        for (int nt = 0; nt < 2; ++nt) {
            *(float2*)(o + g0 + nt * 8) =
                make_float2(rnd_tf32(oacc[mt][nt][0] * i0),
                            rnd_tf32(oacc[mt][nt][1] * i0));
            *(float2*)(o + g1 + nt * 8) =
                make_float2(rnd_tf32(oacc[mt][nt][2] * i1),
                            rnd_tf32(oacc[mt][nt][3] * i1));
        }
    }
}

// ---------------------------------------------------------------------------
// Launch
// ---------------------------------------------------------------------------
extern "C" void kernel_launch(void* const* d_in, const int* in_sizes, int n_in,
                              void* d_out, int out_size)
{
    const float* x     = (const float*)d_in[0];
    const float* ln1_g = (const float*)d_in[1];
    const float* ln1_b = (const float*)d_in[2];
    const float* w_qkv = (const float*)d_in[3];
    const float* w_out = (const float*)d_in[4];
    const float* b_out = (const float*)d_in[5];
    const float* ln2_g = (const float*)d_in[6];
    const float* ln2_b = (const float*)d_in[7];
    const float* w1    = (const float*)d_in[8];
    const float* b1    = (const float*)d_in[9];
    const float* w2    = (const float*)d_in[10];
    const float* b2    = (const float*)d_in[11];
    float* out = (float*)d_out;

    float *h, *qkv, *o, *mid, *wqkv_t, *wout_t, *w1_t, *w2_t;
    cudaGetSymbolAddress((void**)&h,      g_h);
    cudaGetSymbolAddress((void**)&qkv,    g_qkv);
    cudaGetSymbolAddress((void**)&o,      g_o);
    cudaGetSymbolAddress((void**)&mid,    g_mid);
    cudaGetSymbolAddress((void**)&wqkv_t, g_wqkv_t);
    cudaGetSymbolAddress((void**)&wout_t, g_wout_t);
    cudaGetSymbolAddress((void**)&w1_t,   g_w1_t);
    cudaGetSymbolAddress((void**)&w2_t,   g_w2_t);

    cudaFuncSetAttribute(attn_mma_kernel,
                         cudaFuncAttributeMaxDynamicSharedMemorySize, ATT_SMEM_BYTES);
    cudaFuncSetAttribute((const void*)mma_gemm_kernel<false, false>,
                         cudaFuncAttributeMaxDynamicSharedMemorySize, GEMM_SMEM_BYTES);
    cudaFuncSetAttribute((const void*)mma_gemm_kernel<false, true>,
                         cudaFuncAttributeMaxDynamicSharedMemorySize, GEMM_SMEM_BYTES);
    cudaFuncSetAttribute((const void*)mma_gemm_kernel<true, true>,
                         cudaFuncAttributeMaxDynamicSharedMemorySize, GEMM_SMEM_BYTES);

    dim3 tb(32, 8);
    // 0. Transpose weights to [N,K] (tf32-rounded)
    transpose_kernel<<<dim3(QKV_DIM / 32, C_DIM / 32), tb>>>(w_qkv, wqkv_t, C_DIM, QKV_DIM);
    transpose_kernel<<<dim3(C_DIM / 32, C_DIM / 32),   tb>>>(w_out, wout_t, C_DIM, C_DIM);
    transpose_kernel<<<dim3(MLP_DIM / 32, C_DIM / 32), tb>>>(w1, w1_t, C_DIM, MLP_DIM);
    transpose_kernel<<<dim3(C_DIM / 32, MLP_DIM / 32), tb>>>(w2, w2_t, MLP_DIM, C_DIM);

    // 1. h = tf32(LN1(x))
    ln_kernel<<<M_TOK, 256>>>(x, ln1_g, ln1_b, h);

    // 2. qkv = tf32(h @ w_qkv)
    mma_gemm_kernel<false, true><<<dim3(QKV_DIM / 128, M_TOK / 128), 256, GEMM_SMEM_BYTES>>>(
        h, wqkv_t, nullptr, nullptr, qkv, M_TOK, QKV_DIM, C_DIM);

    // 3. o = tf32(attention(qkv))
    attn_mma_kernel<<<dim3(8 * NHEAD, 1024 / 128), 256, ATT_SMEM_BYTES>>>(qkv, o);

    // 4. out = o @ w_out + b_out + x
    mma_gemm_kernel<false, false><<<dim3(C_DIM / 128, M_TOK / 128), 256, GEMM_SMEM_BYTES>>>(
        o, wout_t, b_out, x, out, M_TOK, C_DIM, C_DIM);

    // 5. h = tf32(LN2(out))
    ln_kernel<<<M_TOK, 256>>>(out, ln2_g, ln2_b, h);

    // 6. mid = tf32(gelu(h @ w1 + b1))
    mma_gemm_kernel<true, true><<<dim3(MLP_DIM / 128, M_TOK / 128), 256, GEMM_SMEM_BYTES>>>(
        h, w1_t, b1, nullptr, mid, M_TOK, MLP_DIM, C_DIM);

    // 7. out = out + mid @ w2 + b2
    mma_gemm_kernel<false, false><<<dim3(C_DIM / 128, M_TOK / 128), 256, GEMM_SMEM_BYTES>>>(
        mid, w2_t, b2, out, out, M_TOK, C_DIM, MLP_DIM);
}

// round 10
// speedup vs baseline: 4.4778x; 1.3420x over previous
#include <cuda_runtime.h>
#include <cuda_fp16.h>
#include <math.h>
#include <stdint.h>

// ---------------------------------------------------------------------------
// TransformerBlock: B=8, N=1024, C=768, H=12, Dh=64, MLP=3072, tokens M=8192
// Round 9: GEMMs on fp16 mma.sync m16n8k16 (fp32 accum). Producer-side fp16
// rounding. Attention unchanged (tf32 mma, fp32 qkv), epilogue writes half.
// ---------------------------------------------------------------------------

#define M_TOK   8192
#define C_DIM   768
#define QKV_DIM 2304
#define MLP_DIM 3072
#define NHEAD   12
#define DH      64

// Scratch (allocation-free rule: __device__ globals)
__device__ __half g_h[M_TOK * C_DIM];        // LN out (fp16, GEMM A)
__device__ float  g_qkv[M_TOK * QKV_DIM];    // qkv (fp32 tf32-rounded, attn)
__device__ __half g_o[M_TOK * C_DIM];        // attn out (fp16, GEMM A)
__device__ __half g_mid[M_TOK * MLP_DIM];    // mlp hidden (fp16, GEMM A)
__device__ __half g_wqkv_t[QKV_DIM * C_DIM]; // weights [N][K] fp16
__device__ __half g_wout_t[C_DIM * C_DIM];
__device__ __half g_w1_t[MLP_DIM * C_DIM];
__device__ __half g_w2_t[C_DIM * MLP_DIM];

// ---------------------------------------------------------------------------
// PTX helpers
// ---------------------------------------------------------------------------
__device__ __forceinline__ uint32_t smem_u32(const void* p) {
    uint32_t a;
    asm("{ .reg .u64 t; cvta.to.shared.u64 t, %1; cvt.u32.u64 %0, t; }"
        : "=r"(a) : "l"(p));
    return a;
}

__device__ __forceinline__ void cp_async16(uint32_t dst, const void* src) {
    asm volatile("cp.async.cg.shared.global [%0], [%1], 16;"
                 :: "r"(dst), "l"(src) : "memory");
}
#define CP_ASYNC_COMMIT() asm volatile("cp.async.commit_group;" ::: "memory")
#define CP_ASYNC_WAIT_1() asm volatile("cp.async.wait_group 1;" ::: "memory")
#define CP_ASYNC_WAIT_0() asm volatile("cp.async.wait_group 0;" ::: "memory")

__device__ __forceinline__ float rnd_tf32(float f) {
    uint32_t u;
    asm("cvt.rna.tf32.f32 %0, %1;" : "=r"(u) : "f"(f));
    return __uint_as_float(u);
}

// tf32 mma (attention only)
__device__ __forceinline__ void mma_tf32(float c[4], const uint32_t a[4],
                                         const uint32_t b[2]) {
    asm volatile(
        "mma.sync.aligned.m16n8k8.row.col.f32.tf32.tf32.f32 "
        "{%0,%1,%2,%3}, {%4,%5,%6,%7}, {%8,%9}, {%0,%1,%2,%3};"
        : "+f"(c[0]), "+f"(c[1]), "+f"(c[2]), "+f"(c[3])
        : "r"(a[0]), "r"(a[1]), "r"(a[2]), "r"(a[3]), "r"(b[0]), "r"(b[1]));
}

// fp16 mma, fp32 accumulate (GEMMs)
__device__ __forceinline__ void mma_f16(float c[4], const uint32_t a[4],
                                        const uint32_t b[2]) {
    asm volatile(
        "mma.sync.aligned.m16n8k16.row.col.f32.f16.f16.f32 "
        "{%0,%1,%2,%3}, {%4,%5,%6,%7}, {%8,%9}, {%0,%1,%2,%3};"
        : "+f"(c[0]), "+f"(c[1]), "+f"(c[2]), "+f"(c[3])
        : "r"(a[0]), "r"(a[1]), "r"(a[2]), "r"(a[3]), "r"(b[0]), "r"(b[1]));
}

// ---------------------------------------------------------------------------
// Weight transpose: out[C][R] = fp16(in[R][C])
// ---------------------------------------------------------------------------
__global__ __launch_bounds__(256) void transpose_h_kernel(
    const float* __restrict__ in, __half* __restrict__ out, int R, int C)
{
    __shared__ float t[32][33];
    int bx = blockIdx.x * 32;
    int by = blockIdx.y * 32;
    int x = threadIdx.x, y = threadIdx.y;  // 32 x 8
    #pragma unroll
    for (int i = 0; i < 32; i += 8)
        t[y + i][x] = in[(size_t)(by + y + i) * C + bx + x];
    __syncthreads();
    #pragma unroll
    for (int i = 0; i < 32; i += 8)
        out[(size_t)(bx + y + i) * R + by + x] = __float2half_rn(t[x][y + i]);
}

// ---------------------------------------------------------------------------
// LayerNorm -> fp16
// ---------------------------------------------------------------------------
__global__ __launch_bounds__(256) void ln_kernel(
    const float* __restrict__ x, const float* __restrict__ g,
    const float* __restrict__ b, __half* __restrict__ out)
{
    int row = blockIdx.x;
    int tid = threadIdx.x;
    const float* xr = x + (size_t)row * C_DIM;

    float v0 = xr[tid];
    float v1 = xr[tid + 256];
    float v2 = xr[tid + 512];

    float s  = v0 + v1 + v2;
    float sq = v0 * v0 + v1 * v1 + v2 * v2;

    #pragma unroll
    for (int o = 16; o > 0; o >>= 1) {
        s  += __shfl_xor_sync(0xffffffffu, s,  o);
        sq += __shfl_xor_sync(0xffffffffu, sq, o);
    }

    __shared__ float ss[8], ssq[8];
    __shared__ float mu_s, rs_s;
    int w = tid >> 5;
    if ((tid & 31) == 0) { ss[w] = s; ssq[w] = sq; }
    __syncthreads();
    if (tid == 0) {
        float S = 0.f, SQ = 0.f;
        #pragma unroll
        for (int i = 0; i < 8; ++i) { S += ss[i]; SQ += ssq[i]; }
        float mu  = S * (1.0f / 768.0f);
        float var = SQ * (1.0f / 768.0f) - mu * mu;
        mu_s = mu;
        rs_s = rsqrtf(var + 1e-5f);
    }
    __syncthreads();
    float mu = mu_s, rs = rs_s;

    __half* orow = out + (size_t)row * C_DIM;
    orow[tid]       = __float2half_rn((v0 - mu) * rs * g[tid]       + b[tid]);
    orow[tid + 256] = __float2half_rn((v1 - mu) * rs * g[tid + 256] + b[tid + 256]);
    orow[tid + 512] = __float2half_rn((v2 - mu) * rs * g[tid + 512] + b[tid + 512]);
}

// ---------------------------------------------------------------------------
// fp16 mma.sync GEMM: C = A[M,K] @ Bt[N,K]^T (+bias) (+gelu) (+residual fp32)
// A, Bt fp16. CTA 128x128, BK=32, 8 warps (2x4), warp tile 64x32.
// smem rows stride 40 halves (20 words -> conflict-free fragment LDS).
// OMODE: 0 = fp32 out, 1 = fp32 tf32-rounded out, 2 = fp16 out.
// ---------------------------------------------------------------------------
#define SH 40                                  // smem stride in halves
#define GBUF_HALVES (2 * 128 * SH)             // A+B per buffer
#define GEMM_SMEM_BYTES (2 * GBUF_HALVES * 2)  // 40960

template <bool GELU, int OMODE>
__global__ __launch_bounds__(256, 2)
void hgemm_kernel(const __half* __restrict__ A, const __half* __restrict__ Bt,
                  const float* __restrict__ bias, const float* __restrict__ R,
                  void* __restrict__ Cv, int M, int N, int K)
{
    extern __shared__ __half smh[];
    const uint32_t sm_addr = smem_u32(smh);

    const int tid = threadIdx.x;
    const int wid = tid >> 5;
    const int lane = tid & 31;
    const int tr = lane >> 2;     // 0..7
    const int tc = lane & 3;      // 0..3
    const int warp_m = wid >> 2;  // 0..1
    const int warp_n = wid & 3;   // 0..3
    const int bm = blockIdx.y << 7;
    const int bn = blockIdx.x << 7;

    float acc[4][4][4];
    #pragma unroll
    for (int mt = 0; mt < 4; ++mt)
        #pragma unroll
        for (int nt = 0; nt < 4; ++nt)
            #pragma unroll
            for (int q = 0; q < 4; ++q) acc[mt][nt][q] = 0.f;

    const int nc = K >> 5;

    // one K-chunk (128 rows x 32 halves per operand) -> buffer `buf`
    auto load_chunk = [&](int c, int buf) {
        uint32_t abase = sm_addr + buf * (GBUF_HALVES * 2);
        uint32_t bbase = abase + 128 * SH * 2;
        const __half* ag = A  + (size_t)bm * K + (size_t)(c << 5);
        const __half* bg = Bt + (size_t)bn * K + (size_t)(c << 5);
        #pragma unroll
        for (int it = 0; it < 2; ++it) {
            int flat = tid + it * 256;      // 0..511
            int row  = flat >> 2;           // 0..127
            int seg  = flat & 3;            // 0..3 (x8 halves)
            uint32_t soff = (uint32_t)(row * SH + seg * 8) * 2;
            cp_async16(abase + soff, ag + (size_t)row * K + seg * 8);
            cp_async16(bbase + soff, bg + (size_t)row * K + seg * 8);
        }
        CP_ASYNC_COMMIT();
    };

    load_chunk(0, 0);

    for (int c = 0; c < nc; ++c) {
        if (c + 1 < nc) load_chunk(c + 1, (c + 1) & 1);
        else            CP_ASYNC_COMMIT();
        CP_ASYNC_WAIT_1();
        __syncthreads();

        const __half* Asm = smh + (c & 1) * GBUF_HALVES;
        const __half* Bsm = Asm + 128 * SH;
        const __half* a_ptr = Asm + (warp_m * 64 + tr) * SH + tc * 2;
        const __half* b_ptr = Bsm + (warp_n * 32 + tr) * SH + tc * 2;

        #pragma unroll
        for (int ks = 0; ks < 2; ++ks) {    // two k16 steps cover BK=32
            uint32_t af[4][4], bf[4][2];
            #pragma unroll
            for (int mt = 0; mt < 4; ++mt) {
                const __half* p = a_ptr + mt * 16 * SH + ks * 16;
                af[mt][0] = *(const uint32_t*)(p);
                af[mt][1] = *(const uint32_t*)(p + 8 * SH);
                af[mt][2] = *(const uint32_t*)(p + 8);
                af[mt][3] = *(const uint32_t*)(p + 8 * SH + 8);
            }
            #pragma unroll
            for (int nt = 0; nt < 4; ++nt) {
                const __half* p = b_ptr + nt * 8 * SH + ks * 16;
                bf[nt][0] = *(const uint32_t*)(p);
                bf[nt][1] = *(const uint32_t*)(p + 8);
            }
            #pragma unroll
            for (int mt = 0; mt < 4; ++mt)
                #pragma unroll
                for (int nt = 0; nt < 4; ++nt)
                    mma_f16(acc[mt][nt], af[mt], bf[nt]);
        }
        __syncthreads();
    }

    const int row0 = bm + warp_m * 64 + tr;
    const int col0 = bn + warp_n * 32 + tc * 2;

    float2 bp[4];
    #pragma unroll
    for (int nt = 0; nt < 4; ++nt) {
        if (bias) {
            bp[nt].x = __ldg(&bias[col0 + nt * 8]);
            bp[nt].y = __ldg(&bias[col0 + nt * 8 + 1]);
        } else {
            bp[nt].x = 0.f; bp[nt].y = 0.f;
        }
    }

    #pragma unroll
    for (int mt = 0; mt < 4; ++mt) {
        #pragma unroll
        for (int half_i = 0; half_i < 2; ++half_i) {
            int r = row0 + mt * 16 + half_i * 8;
            const float* Rp = R ? (R + (size_t)r * N) : nullptr;
            #pragma unroll
            for (int nt = 0; nt < 4; ++nt) {
                int cl = col0 + nt * 8;
                float v0 = acc[mt][nt][half_i * 2 + 0] + bp[nt].x;
                float v1 = acc[mt][nt][half_i * 2 + 1] + bp[nt].y;
                if (GELU) { v0 *= normcdff(v0); v1 *= normcdff(v1); }
                if (Rp) {
                    float2 rv = *(const float2*)(Rp + cl);
                    v0 += rv.x; v1 += rv.y;
                }
                if (OMODE == 2) {
                    *(__half2*)((__half*)Cv + (size_t)r * N + cl) =
                        __floats2half2_rn(v0, v1);
                } else {
                    if (OMODE == 1) { v0 = rnd_tf32(v0); v1 = rnd_tf32(v1); }
                    *(float2*)((float*)Cv + (size_t)r * N + cl) =
                        make_float2(v0, v1);
                }
            }
        }
    }
}

// ---------------------------------------------------------------------------
// Flash attention via tf32 mma (unchanged internals; epilogue -> fp16)
// ---------------------------------------------------------------------------
#define QS   68
#define SSTR 132
#define ATT_SMEM_BYTES ((3 * 128 * QS + 128 * SSTR + 128) * 4)

__global__ __launch_bounds__(256, 1) void attn_mma_kernel(
    const float* __restrict__ qkv, __half* __restrict__ o)
{
    extern __shared__ float sm[];
    float* Qs   = sm;
    float* Ks   = Qs + 128 * QS;
    float* Vs   = Ks + 128 * QS;
    float* Ss   = Vs + 128 * QS;
    float* srow = Ss + 128 * SSTR;

    const uint32_t Qs_a = smem_u32(Qs);
    const uint32_t Ks_a = smem_u32(Ks);
    const uint32_t Vs_a = smem_u32(Vs);

    const int b = blockIdx.x / NHEAD;
    const int h = blockIdx.x % NHEAD;
    const int q0 = blockIdx.y << 7;
    const int tid = threadIdx.x;
    const int wid = tid >> 5, lane = tid & 31;
    const int tr = lane >> 2, tc = lane & 3;
    const int warp_m = wid >> 2;
    const int warp_n = wid & 3;

    const float* base = qkv + (size_t)b * 1024 * QKV_DIM + h * DH;

    {
        const int row = tid >> 1, half_i = tid & 1;
        const float* src = base + (size_t)(q0 + row) * QKV_DIM + half_i * 32;
        uint32_t dst = Qs_a + (uint32_t)(row * QS + half_i * 32) * 4;
        #pragma unroll
        for (int i = 0; i < 8; ++i) cp_async16(dst + i * 16, src + i * 4);
        CP_ASYNC_COMMIT();
    }

    float oacc[4][2][4];
    #pragma unroll
    for (int mt = 0; mt < 4; ++mt)
        #pragma unroll
        for (int nt = 0; nt < 2; ++nt)
            #pragma unroll
            for (int q = 0; q < 4; ++q) oacc[mt][nt][q] = 0.f;

    float m_run = -INFINITY, l_run = 0.f;

    for (int kc = 0; kc < 8; ++kc) {
        __syncthreads();

        {
            const int row = tid >> 1, half_i = tid & 1;
            const float* ksrc = base + (size_t)(kc * 128 + row) * QKV_DIM + 768 + half_i * 32;
            uint32_t kdst = Ks_a + (uint32_t)(row * QS + half_i * 32) * 4;
            #pragma unroll
            for (int i = 0; i < 8; ++i) cp_async16(kdst + i * 16, ksrc + i * 4);
            CP_ASYNC_COMMIT();
            const float* vsrc = ksrc + 768;
            uint32_t vdst = Vs_a + (uint32_t)(row * QS + half_i * 32) * 4;
            #pragma unroll
            for (int i = 0; i < 8; ++i) cp_async16(vdst + i * 16, vsrc + i * 4);
            CP_ASYNC_COMMIT();
        }
        CP_ASYNC_WAIT_1();
        __syncthreads();

        float sacc[4][4][4];
        #pragma unroll
        for (int mt = 0; mt < 4; ++mt)
            #pragma unroll
            for (int nt = 0; nt < 4; ++nt)
                #pragma unroll
                for (int q = 0; q < 4; ++q) sacc[mt][nt][q] = 0.f;

        const float* a_base = Qs + (warp_m * 64 + tr) * QS + tc;
        const float* b_base = Ks + (warp_n * 32 + tr) * QS + tc;
        #pragma unroll
        for (int ksi = 0; ksi < 8; ++ksi) {
            uint32_t af[4][4], bf[4][2];
            #pragma unroll
            for (int mt = 0; mt < 4; ++mt) {
                const float* p = a_base + mt * 16 * QS + ksi * 8;
                af[mt][0] = __float_as_uint(p[0]);
                af[mt][1] = __float_as_uint(p[8 * QS]);
                af[mt][2] = __float_as_uint(p[4]);
                af[mt][3] = __float_as_uint(p[8 * QS + 4]);
            }
            #pragma unroll
            for (int nt = 0; nt < 4; ++nt) {
                const float* p = b_base + nt * 8 * QS + ksi * 8;
                bf[nt][0] = __float_as_uint(p[0]);
                bf[nt][1] = __float_as_uint(p[4]);
            }
            #pragma unroll
            for (int mt = 0; mt < 4; ++mt)
                #pragma unroll
                for (int nt = 0; nt < 4; ++nt)
                    mma_tf32(sacc[mt][nt], af[mt], bf[nt]);
        }
        #pragma unroll
        for (int mt = 0; mt < 4; ++mt) {
            int r0 = warp_m * 64 + mt * 16 + tr;
            #pragma unroll
            for (int nt = 0; nt < 4; ++nt) {
                int c0 = warp_n * 32 + nt * 8 + tc * 2;
                *(float2*)&Ss[r0 * SSTR + c0] =
                    make_float2(sacc[mt][nt][0], sacc[mt][nt][1]);
                *(float2*)&Ss[(r0 + 8) * SSTR + c0] =
                    make_float2(sacc[mt][nt][2], sacc[mt][nt][3]);
            }
        }
        __syncthreads();

        if (tid < 128) {
            float* srr = &Ss[tid * SSTR];
            float mx = -INFINITY;
            #pragma unroll 8
            for (int c4 = 0; c4 < 32; ++c4) {
                float4 v = *(const float4*)&srr[c4 * 4];
                mx = fmaxf(mx, fmaxf(fmaxf(v.x, v.y), fmaxf(v.z, v.w)));
            }
            float m_new = fmaxf(m_run, 0.125f * mx);
            float scl = __expf(m_run - m_new);
            float ls = 0.f;
            #pragma unroll 8
            for (int c4 = 0; c4 < 32; ++c4) {
                float4 v = *(const float4*)&srr[c4 * 4];
                v.x = rnd_tf32(__expf(fmaf(0.125f, v.x, -m_new)));
                v.y = rnd_tf32(__expf(fmaf(0.125f, v.y, -m_new)));
                v.z = rnd_tf32(__expf(fmaf(0.125f, v.z, -m_new)));
                v.w = rnd_tf32(__expf(fmaf(0.125f, v.w, -m_new)));
                ls += v.x + v.y + v.z + v.w;
                *(float4*)&srr[c4 * 4] = v;
            }
            l_run = l_run * scl + ls;
            m_run = m_new;
            srow[tid] = scl;
        }
        CP_ASYNC_WAIT_0();
        __syncthreads();

        #pragma unroll
        for (int mt = 0; mt < 4; ++mt) {
            float s0 = srow[warp_m * 64 + mt * 16 + tr];
            float s1 = srow[warp_m * 64 + mt * 16 + tr + 8];
            #pragma unroll
            for (int nt = 0; nt < 2; ++nt) {
                oacc[mt][nt][0] *= s0; oacc[mt][nt][1] *= s0;
                oacc[mt][nt][2] *= s1; oacc[mt][nt][3] *= s1;
            }
        }
        const float* pa_base = Ss + (warp_m * 64 + tr) * SSTR + tc;
        const float* vb_base = Vs + tc * QS + warp_n * 16 + tr;
        #pragma unroll
        for (int ksi = 0; ksi < 16; ++ksi) {
            uint32_t af[4][4], bf[2][2];
            #pragma unroll
            for (int mt = 0; mt < 4; ++mt) {
                const float* p = pa_base + mt * 16 * SSTR + ksi * 8;
                af[mt][0] = __float_as_uint(p[0]);
                af[mt][1] = __float_as_uint(p[8 * SSTR]);
                af[mt][2] = __float_as_uint(p[4]);
                af[mt][3] = __float_as_uint(p[8 * SSTR + 4]);
            }
            #pragma unroll
            for (int nt = 0; nt < 2; ++nt) {
                const float* p = vb_base + ksi * 8 * QS + nt * 8;
                bf[nt][0] = __float_as_uint(p[0]);
                bf[nt][1] = __float_as_uint(p[4 * QS]);
            }
            #pragma unroll
            for (int mt = 0; mt < 4; ++mt)
                #pragma unroll
                for (int nt = 0; nt < 2; ++nt)
                    mma_tf32(oacc[mt][nt], af[mt], bf[nt]);
        }
    }

    __syncthreads();
    if (tid < 128) srow[tid] = 1.0f / l_run;
    __syncthreads();

    // epilogue: fp16 (feeds out-proj GEMM A operand)
    #pragma unroll
    for (int mt = 0; mt < 4; ++mt) {
        int r0 = warp_m * 64 + mt * 16 + tr;
        float i0 = srow[r0], i1 = srow[r0 + 8];
        size_t g0 = ((size_t)b * 1024 + q0 + r0) * C_DIM + h * DH
                    + warp_n * 16 + tc * 2;
        size_t g1 = g0 + (size_t)8 * C_DIM;
        #pragma unroll
        for (int nt = 0; nt < 2; ++nt) {
            *(__half2*)(o + g0 + nt * 8) =
                __floats2half2_rn(oacc[mt][nt][0] * i0, oacc[mt][nt][1] * i0);
            *(__half2*)(o + g1 + nt * 8) =
                __floats2half2_rn(oacc[mt][nt][2] * i1, oacc[mt][nt][3] * i1);
        }
    }
}

// ---------------------------------------------------------------------------
// Launch
// ---------------------------------------------------------------------------
extern "C" void kernel_launch(void* const* d_in, const int* in_sizes, int n_in,
                              void* d_out, int out_size)
{
    const float* x     = (const float*)d_in[0];
    const float* ln1_g = (const float*)d_in[1];
    const float* ln1_b = (const float*)d_in[2];
    const float* w_qkv = (const float*)d_in[3];
    const float* w_out = (const float*)d_in[4];
    const float* b_out = (const float*)d_in[5];
    const float* ln2_g = (const float*)d_in[6];
    const float* ln2_b = (const float*)d_in[7];
    const float* w1    = (const float*)d_in[8];
    const float* b1    = (const float*)d_in[9];
    const float* w2    = (const float*)d_in[10];
    const float* b2    = (const float*)d_in[11];
    float* out = (float*)d_out;

    __half *h, *o, *mid, *wqkv_t, *wout_t, *w1_t, *w2_t;
    float *qkv;
    cudaGetSymbolAddress((void**)&h,      g_h);
    cudaGetSymbolAddress((void**)&qkv,    g_qkv);
    cudaGetSymbolAddress((void**)&o,      g_o);
    cudaGetSymbolAddress((void**)&mid,    g_mid);
    cudaGetSymbolAddress((void**)&wqkv_t, g_wqkv_t);
    cudaGetSymbolAddress((void**)&wout_t, g_wout_t);
    cudaGetSymbolAddress((void**)&w1_t,   g_w1_t);
    cudaGetSymbolAddress((void**)&w2_t,   g_w2_t);

    cudaFuncSetAttribute(attn_mma_kernel,
                         cudaFuncAttributeMaxDynamicSharedMemorySize, ATT_SMEM_BYTES);
    cudaFuncSetAttribute((const void*)hgemm_kernel<false, 0>,
                         cudaFuncAttributeMaxDynamicSharedMemorySize, GEMM_SMEM_BYTES);
    cudaFuncSetAttribute((const void*)hgemm_kernel<false, 1>,
                         cudaFuncAttributeMaxDynamicSharedMemorySize, GEMM_SMEM_BYTES);
    cudaFuncSetAttribute((const void*)hgemm_kernel<true, 2>,
                         cudaFuncAttributeMaxDynamicSharedMemorySize, GEMM_SMEM_BYTES);

    dim3 tb(32, 8);
    // 0. Transpose weights to [N][K] fp16
    transpose_h_kernel<<<dim3(QKV_DIM / 32, C_DIM / 32), tb>>>(w_qkv, wqkv_t, C_DIM, QKV_DIM);
    transpose_h_kernel<<<dim3(C_DIM / 32, C_DIM / 32),   tb>>>(w_out, wout_t, C_DIM, C_DIM);
    transpose_h_kernel<<<dim3(MLP_DIM / 32, C_DIM / 32), tb>>>(w1, w1_t, C_DIM, MLP_DIM);
    transpose_h_kernel<<<dim3(C_DIM / 32, MLP_DIM / 32), tb>>>(w2, w2_t, MLP_DIM, C_DIM);

    // 1. h = fp16(LN1(x))
    ln_kernel<<<M_TOK, 256>>>(x, ln1_g, ln1_b, h);

    // 2. qkv = tf32(h @ w_qkv)   (fp32 out for attention)
    hgemm_kernel<false, 1><<<dim3(QKV_DIM / 128, M_TOK / 128), 256, GEMM_SMEM_BYTES>>>(
        h, wqkv_t, nullptr, nullptr, qkv, M_TOK, QKV_DIM, C_DIM);

    // 3. o = fp16(attention(qkv))
    attn_mma_kernel<<<dim3(8 * NHEAD, 1024 / 128), 256, ATT_SMEM_BYTES>>>(qkv, o);

    // 4. out = o @ w_out + b_out + x   (fp32)
    hgemm_kernel<false, 0><<<dim3(C_DIM / 128, M_TOK / 128), 256, GEMM_SMEM_BYTES>>>(
        o, wout_t, b_out, x, out, M_TOK, C_DIM, C_DIM);

    // 5. h = fp16(LN2(out))
    ln_kernel<<<M_TOK, 256>>>(out, ln2_g, ln2_b, h);

    // 6. mid = fp16(gelu(h @ w1 + b1))
    hgemm_kernel<true, 2><<<dim3(MLP_DIM / 128, M_TOK / 128), 256, GEMM_SMEM_BYTES>>>(
        h, w1_t, b1, nullptr, mid, M_TOK, MLP_DIM, C_DIM);

    // 7. out = out + mid @ w2 + b2   (fp32)
    hgemm_kernel<false, 0><<<dim3(C_DIM / 128, M_TOK / 128), 256, GEMM_SMEM_BYTES>>>(
        mid, w2_t, b2, out, out, M_TOK, C_DIM, MLP_DIM);
}

// round 12
// speedup vs baseline: 5.0992x; 1.1388x over previous
#include <cuda_runtime.h>
#include <cuda_fp16.h>
#include <math.h>
#include <stdint.h>

// ---------------------------------------------------------------------------
// TransformerBlock: B=8, N=1024, C=768, H=12, Dh=64, MLP=3072, tokens M=8192
// Round 11: ldmatrix fragment loads in GEMM; attention fully fp16
// (m16n8k16 + ldmatrix/.trans), fp16 smem tiles.
// ---------------------------------------------------------------------------

#define M_TOK   8192
#define C_DIM   768
#define QKV_DIM 2304
#define MLP_DIM 3072
#define NHEAD   12
#define DH      64

// Scratch (allocation-free rule: __device__ globals)
__device__ __half g_h[M_TOK * C_DIM];        // LN out
__device__ __half g_qkv[M_TOK * QKV_DIM];    // qkv (fp16)
__device__ __half g_o[M_TOK * C_DIM];        // attn out
__device__ __half g_mid[M_TOK * MLP_DIM];    // mlp hidden
__device__ __half g_wqkv_t[QKV_DIM * C_DIM]; // weights [N][K]
__device__ __half g_wout_t[C_DIM * C_DIM];
__device__ __half g_w1_t[MLP_DIM * C_DIM];
__device__ __half g_w2_t[C_DIM * MLP_DIM];

// ---------------------------------------------------------------------------
// PTX helpers
// ---------------------------------------------------------------------------
__device__ __forceinline__ uint32_t smem_u32(const void* p) {
    uint32_t a;
    asm("{ .reg .u64 t; cvta.to.shared.u64 t, %1; cvt.u32.u64 %0, t; }"
        : "=r"(a) : "l"(p));
    return a;
}

__device__ __forceinline__ void cp_async16(uint32_t dst, const void* src) {
    asm volatile("cp.async.cg.shared.global [%0], [%1], 16;"
                 :: "r"(dst), "l"(src) : "memory");
}
#define CP_ASYNC_COMMIT() asm volatile("cp.async.commit_group;" ::: "memory")
#define CP_ASYNC_WAIT_1() asm volatile("cp.async.wait_group 1;" ::: "memory")
#define CP_ASYNC_WAIT_0() asm volatile("cp.async.wait_group 0;" ::: "memory")

__device__ __forceinline__ void ldsm_x4(uint32_t r[4], uint32_t addr) {
    asm volatile("ldmatrix.sync.aligned.m8n8.x4.shared.b16 {%0,%1,%2,%3}, [%4];"
                 : "=r"(r[0]), "=r"(r[1]), "=r"(r[2]), "=r"(r[3]) : "r"(addr));
}
__device__ __forceinline__ void ldsm_x4_t(uint32_t r[4], uint32_t addr) {
    asm volatile("ldmatrix.sync.aligned.m8n8.x4.trans.shared.b16 {%0,%1,%2,%3}, [%4];"
                 : "=r"(r[0]), "=r"(r[1]), "=r"(r[2]), "=r"(r[3]) : "r"(addr));
}

// fp16 mma, fp32 accumulate
__device__ __forceinline__ void mma_f16(float c[4], const uint32_t a[4],
                                        const uint32_t b[2]) {
    asm volatile(
        "mma.sync.aligned.m16n8k16.row.col.f32.f16.f16.f32 "
        "{%0,%1,%2,%3}, {%4,%5,%6,%7}, {%8,%9}, {%0,%1,%2,%3};"
        : "+f"(c[0]), "+f"(c[1]), "+f"(c[2]), "+f"(c[3])
        : "r"(a[0]), "r"(a[1]), "r"(a[2]), "r"(a[3]), "r"(b[0]), "r"(b[1]));
}

// ---------------------------------------------------------------------------
// Weight transpose: out[C][R] = fp16(in[R][C])
// ---------------------------------------------------------------------------
__global__ __launch_bounds__(256) void transpose_h_kernel(
    const float* __restrict__ in, __half* __restrict__ out, int R, int C)
{
    __shared__ float t[32][33];
    int bx = blockIdx.x * 32;
    int by = blockIdx.y * 32;
    int x = threadIdx.x, y = threadIdx.y;  // 32 x 8
    #pragma unroll
    for (int i = 0; i < 32; i += 8)
        t[y + i][x] = in[(size_t)(by + y + i) * C + bx + x];
    __syncthreads();
    #pragma unroll
    for (int i = 0; i < 32; i += 8)
        out[(size_t)(bx + y + i) * R + by + x] = __float2half_rn(t[x][y + i]);
}

// ---------------------------------------------------------------------------
// LayerNorm -> fp16
// ---------------------------------------------------------------------------
__global__ __launch_bounds__(256) void ln_kernel(
    const float* __restrict__ x, const float* __restrict__ g,
    const float* __restrict__ b, __half* __restrict__ out)
{
    int row = blockIdx.x;
    int tid = threadIdx.x;
    const float* xr = x + (size_t)row * C_DIM;

    float v0 = xr[tid];
    float v1 = xr[tid + 256];
    float v2 = xr[tid + 512];

    float s  = v0 + v1 + v2;
    float sq = v0 * v0 + v1 * v1 + v2 * v2;

    #pragma unroll
    for (int o = 16; o > 0; o >>= 1) {
        s  += __shfl_xor_sync(0xffffffffu, s,  o);
        sq += __shfl_xor_sync(0xffffffffu, sq, o);
    }

    __shared__ float ss[8], ssq[8];
    __shared__ float mu_s, rs_s;
    int w = tid >> 5;
    if ((tid & 31) == 0) { ss[w] = s; ssq[w] = sq; }
    __syncthreads();
    if (tid == 0) {
        float S = 0.f, SQ = 0.f;
        #pragma unroll
        for (int i = 0; i < 8; ++i) { S += ss[i]; SQ += ssq[i]; }
        float mu  = S * (1.0f / 768.0f);
        float var = SQ * (1.0f / 768.0f) - mu * mu;
        mu_s = mu;
        rs_s = rsqrtf(var + 1e-5f);
    }
    __syncthreads();
    float mu = mu_s, rs = rs_s;

    __half* orow = out + (size_t)row * C_DIM;
    orow[tid]       = __float2half_rn((v0 - mu) * rs * g[tid]       + b[tid]);
    orow[tid + 256] = __float2half_rn((v1 - mu) * rs * g[tid + 256] + b[tid + 256]);
    orow[tid + 512] = __float2half_rn((v2 - mu) * rs * g[tid + 512] + b[tid + 512]);
}

// ---------------------------------------------------------------------------
// fp16 mma.sync GEMM with ldmatrix fragment loads.
// C = A[M,K] @ Bt[N,K]^T (+bias) (+gelu) (+residual fp32)
// CTA 128x128, BK=32, 8 warps (2x4), warp tile 64x32.
// OMODE: 0 = fp32 out, 2 = fp16 out.
// ---------------------------------------------------------------------------
#define SH 40                                  // smem stride in halves
#define GBUF_HALVES (2 * 128 * SH)
#define GEMM_SMEM_BYTES (2 * GBUF_HALVES * 2)  // 40960

template <bool GELU, int OMODE>
__global__ __launch_bounds__(256, 2)
void hgemm_kernel(const __half* __restrict__ A, const __half* __restrict__ Bt,
                  const float* __restrict__ bias, const float* __restrict__ R,
                  void* __restrict__ Cv, int M, int N, int K)
{
    extern __shared__ __half smh[];
    const uint32_t sm_addr = smem_u32(smh);

    const int tid = threadIdx.x;
    const int wid = tid >> 5;
    const int lane = tid & 31;
    const int tr = lane >> 2;
    const int tc = lane & 3;
    const int warp_m = wid >> 2;
    const int warp_n = wid & 3;
    const int bm = blockIdx.y << 7;
    const int bn = blockIdx.x << 7;

    // ldmatrix lane address bases (bytes, relative to buffer start)
    const int quad = lane >> 3, qr = lane & 7;
    const uint32_t a_off =
        (uint32_t)(((warp_m * 64 + (quad & 1) * 8 + qr) * SH + (quad >> 1) * 8) * 2);
    const uint32_t b_off =
        (uint32_t)(((warp_n * 32 + (quad >> 1) * 8 + qr) * SH + (quad & 1) * 8) * 2
                   + 128 * SH * 2);

    float acc[4][4][4];
    #pragma unroll
    for (int mt = 0; mt < 4; ++mt)
        #pragma unroll
        for (int nt = 0; nt < 4; ++nt)
            #pragma unroll
            for (int q = 0; q < 4; ++q) acc[mt][nt][q] = 0.f;

    const int nc = K >> 5;

    auto load_chunk = [&](int c, int buf) {
        uint32_t abase = sm_addr + buf * (GBUF_HALVES * 2);
        uint32_t bbase = abase + 128 * SH * 2;
        const __half* ag = A  + (size_t)bm * K + (size_t)(c << 5);
        const __half* bg = Bt + (size_t)bn * K + (size_t)(c << 5);
        #pragma unroll
        for (int it = 0; it < 2; ++it) {
            int flat = tid + it * 256;
            int row  = flat >> 2;
            int seg  = flat & 3;
            uint32_t soff = (uint32_t)(row * SH + seg * 8) * 2;
            cp_async16(abase + soff, ag + (size_t)row * K + seg * 8);
            cp_async16(bbase + soff, bg + (size_t)row * K + seg * 8);
        }
        CP_ASYNC_COMMIT();
    };

    load_chunk(0, 0);

    for (int c = 0; c < nc; ++c) {
        if (c + 1 < nc) load_chunk(c + 1, (c + 1) & 1);
        else            CP_ASYNC_COMMIT();
        CP_ASYNC_WAIT_1();
        __syncthreads();

        uint32_t base = sm_addr + (c & 1) * (GBUF_HALVES * 2);

        #pragma unroll
        for (int ks = 0; ks < 2; ++ks) {
            uint32_t af[4][4], bq[2][4];
            #pragma unroll
            for (int mt = 0; mt < 4; ++mt)
                ldsm_x4(af[mt], base + a_off + (uint32_t)((mt * 16 * SH + ks * 16) * 2));
            #pragma unroll
            for (int np = 0; np < 2; ++np)
                ldsm_x4(bq[np], base + b_off + (uint32_t)((np * 16 * SH + ks * 16) * 2));
            #pragma unroll
            for (int mt = 0; mt < 4; ++mt)
                #pragma unroll
                for (int nt = 0; nt < 4; ++nt)
                    mma_f16(acc[mt][nt], af[mt], &bq[nt >> 1][(nt & 1) * 2]);
        }
        __syncthreads();
    }

    const int row0 = bm + warp_m * 64 + tr;
    const int col0 = bn + warp_n * 32 + tc * 2;

    float2 bp[4];
    #pragma unroll
    for (int nt = 0; nt < 4; ++nt) {
        if (bias) {
            bp[nt].x = __ldg(&bias[col0 + nt * 8]);
            bp[nt].y = __ldg(&bias[col0 + nt * 8 + 1]);
        } else {
            bp[nt].x = 0.f; bp[nt].y = 0.f;
        }
    }

    #pragma unroll
    for (int mt = 0; mt < 4; ++mt) {
        #pragma unroll
        for (int half_i = 0; half_i < 2; ++half_i) {
            int r = row0 + mt * 16 + half_i * 8;
            const float* Rp = R ? (R + (size_t)r * N) : nullptr;
            #pragma unroll
            for (int nt = 0; nt < 4; ++nt) {
                int cl = col0 + nt * 8;
                float v0 = acc[mt][nt][half_i * 2 + 0] + bp[nt].x;
                float v1 = acc[mt][nt][half_i * 2 + 1] + bp[nt].y;
                if (GELU) { v0 *= normcdff(v0); v1 *= normcdff(v1); }
                if (Rp) {
                    float2 rv = *(const float2*)(Rp + cl);
                    v0 += rv.x; v1 += rv.y;
                }
                if (OMODE == 2) {
                    *(__half2*)((__half*)Cv + (size_t)r * N + cl) =
                        __floats2half2_rn(v0, v1);
                } else {
                    *(float2*)((float*)Cv + (size_t)r * N + cl) =
                        make_float2(v0, v1);
                }
            }
        }
    }
}

// ---------------------------------------------------------------------------
// fp16 flash attention: CTA = (b, h, 128-query tile), 256 threads.
// S = Q@K^T and O += P@V on m16n8k16 with ldmatrix (trans for V).
// smem (halves): Qh[128][72] Kh[128][72] Vh[128][72] | Ss fp32[128][132] |
//                Ph[128][136] | srow fp32[128]
// ---------------------------------------------------------------------------
#define AS 72
#define PS 136
#define SSTR 132
#define ATT_Q_OFF   0
#define ATT_K_OFF   (128 * AS)
#define ATT_V_OFF   (2 * 128 * AS)
#define ATT_SS_BYTE (3 * 128 * AS * 2)                 // 55296
#define ATT_PH_BYTE (ATT_SS_BYTE + 128 * SSTR * 4)     // 122880
#define ATT_SR_BYTE (ATT_PH_BYTE + 128 * PS * 2)       // 157696
#define ATT_SMEM_BYTES (ATT_SR_BYTE + 128 * 4)         // 158208

__global__ __launch_bounds__(256, 1) void attn_h_kernel(
    const __half* __restrict__ qkv, __half* __restrict__ o)
{
    extern __shared__ __half smh[];
    const uint32_t sb = smem_u32(smh);
    __half* Qh = smh;
    float*  Ss = (float*)((char*)smh + ATT_SS_BYTE);
    __half* Ph = (__half*)((char*)smh + ATT_PH_BYTE);
    float*  srow = (float*)((char*)smh + ATT_SR_BYTE);

    const uint32_t Q_a = sb;
    const uint32_t K_a = sb + ATT_K_OFF * 2;
    const uint32_t V_a = sb + ATT_V_OFF * 2;
    const uint32_t P_a = sb + ATT_PH_BYTE;

    const int b = blockIdx.x / NHEAD;
    const int h = blockIdx.x % NHEAD;
    const int q0 = blockIdx.y << 7;
    const int tid = threadIdx.x;
    const int wid = tid >> 5, lane = tid & 31;
    const int tr = lane >> 2, tc = lane & 3;
    const int warp_m = wid >> 2;
    const int warp_n = wid & 3;
    const int quad = lane >> 3, qr = lane & 7;

    // ldmatrix lane bases (bytes)
    const uint32_t q_lm = Q_a +
        (uint32_t)(((warp_m * 64 + (quad & 1) * 8 + qr) * AS + (quad >> 1) * 8) * 2);
    const uint32_t k_lm = K_a +
        (uint32_t)(((warp_n * 32 + (quad >> 1) * 8 + qr) * AS + (quad & 1) * 8) * 2);
    const uint32_t p_lm = P_a +
        (uint32_t)(((warp_m * 64 + (quad & 1) * 8 + qr) * PS + (quad >> 1) * 8) * 2);
    const uint32_t v_lm = V_a +
        (uint32_t)((((quad & 1) * 8 + qr) * AS + warp_n * 16 + (quad >> 1) * 8) * 2);

    const __half* base = qkv + (size_t)b * 1024 * QKV_DIM + h * DH;

    // Q tile: 128 rows x 64 halves (128B); 2 threads/row, 4 cp.async each
    {
        const int row = tid >> 1, hf = tid & 1;
        const __half* src = base + (size_t)(q0 + row) * QKV_DIM + hf * 32;
        uint32_t dst = Q_a + (uint32_t)((row * AS + hf * 32) * 2);
        #pragma unroll
        for (int i = 0; i < 4; ++i) cp_async16(dst + i * 16, src + i * 8);
        CP_ASYNC_COMMIT();
    }

    float oacc[4][2][4];
    #pragma unroll
    for (int mt = 0; mt < 4; ++mt)
        #pragma unroll
        for (int nt = 0; nt < 2; ++nt)
            #pragma unroll
            for (int q = 0; q < 4; ++q) oacc[mt][nt][q] = 0.f;

    float m_run = -INFINITY, l_run = 0.f;

    for (int kc = 0; kc < 8; ++kc) {
        __syncthreads();   // prev iter PV reads of K/V/Ph done

        {
            const int row = tid >> 1, hf = tid & 1;
            const __half* ksrc = base + (size_t)(kc * 128 + row) * QKV_DIM + 768 + hf * 32;
            uint32_t kdst = K_a + (uint32_t)((row * AS + hf * 32) * 2);
            #pragma unroll
            for (int i = 0; i < 4; ++i) cp_async16(kdst + i * 16, ksrc + i * 8);
            CP_ASYNC_COMMIT();
            const __half* vsrc = ksrc + 768;
            uint32_t vdst = V_a + (uint32_t)((row * AS + hf * 32) * 2);
            #pragma unroll
            for (int i = 0; i < 4; ++i) cp_async16(vdst + i * 16, vsrc + i * 8);
            CP_ASYNC_COMMIT();
        }
        CP_ASYNC_WAIT_1();   // Q (first iter) and K resident
        __syncthreads();

        // ---- S = Q @ K^T ----
        float sacc[4][4][4];
        #pragma unroll
        for (int mt = 0; mt < 4; ++mt)
            #pragma unroll
            for (int nt = 0; nt < 4; ++nt)
                #pragma unroll
                for (int q = 0; q < 4; ++q) sacc[mt][nt][q] = 0.f;

        #pragma unroll
        for (int ks = 0; ks < 4; ++ks) {
            uint32_t af[4][4], bq[2][4];
            #pragma unroll
            for (int mt = 0; mt < 4; ++mt)
                ldsm_x4(af[mt], q_lm + (uint32_t)((mt * 16 * AS + ks * 16) * 2));
            #pragma unroll
            for (int np = 0; np < 2; ++np)
                ldsm_x4(bq[np], k_lm + (uint32_t)((np * 16 * AS + ks * 16) * 2));
            #pragma unroll
            for (int mt = 0; mt < 4; ++mt)
                #pragma unroll
                for (int nt = 0; nt < 4; ++nt)
                    mma_f16(sacc[mt][nt], af[mt], &bq[nt >> 1][(nt & 1) * 2]);
        }
        #pragma unroll
        for (int mt = 0; mt < 4; ++mt) {
            int r0 = warp_m * 64 + mt * 16 + tr;
            #pragma unroll
            for (int nt = 0; nt < 4; ++nt) {
                int c0 = warp_n * 32 + nt * 8 + tc * 2;
                *(float2*)&Ss[r0 * SSTR + c0] =
                    make_float2(sacc[mt][nt][0], sacc[mt][nt][1]);
                *(float2*)&Ss[(r0 + 8) * SSTR + c0] =
                    make_float2(sacc[mt][nt][2], sacc[mt][nt][3]);
            }
        }
        __syncthreads();

        // ---- online softmax (row = tid < 128), P -> fp16 ----
        if (tid < 128) {
            float* srr = &Ss[tid * SSTR];
            __half* prr = &Ph[tid * PS];
            float mx = -INFINITY;
            #pragma unroll 8
            for (int c4 = 0; c4 < 32; ++c4) {
                float4 v = *(const float4*)&srr[c4 * 4];
                mx = fmaxf(mx, fmaxf(fmaxf(v.x, v.y), fmaxf(v.z, v.w)));
            }
            float m_new = fmaxf(m_run, 0.125f * mx);
            float scl = __expf(m_run - m_new);
            float ls = 0.f;
            #pragma unroll 8
            for (int c4 = 0; c4 < 32; ++c4) {
                float4 v = *(const float4*)&srr[c4 * 4];
                __half2 p0 = __floats2half2_rn(__expf(fmaf(0.125f, v.x, -m_new)),
                                               __expf(fmaf(0.125f, v.y, -m_new)));
                __half2 p1 = __floats2half2_rn(__expf(fmaf(0.125f, v.z, -m_new)),
                                               __expf(fmaf(0.125f, v.w, -m_new)));
                *(__half2*)&prr[c4 * 4]     = p0;
                *(__half2*)&prr[c4 * 4 + 2] = p1;
                float2 f0 = __half22float2(p0), f1 = __half22float2(p1);
                ls += (f0.x + f0.y) + (f1.x + f1.y);   // sum of rounded p
            }
            l_run = l_run * scl + ls;
            m_run = m_new;
            srow[tid] = scl;
        }
        CP_ASYNC_WAIT_0();   // V resident
        __syncthreads();     // Ph, srow, V visible

        // ---- O = O*scl + P @ V ----
        #pragma unroll
        for (int mt = 0; mt < 4; ++mt) {
            float s0 = srow[warp_m * 64 + mt * 16 + tr];
            float s1 = srow[warp_m * 64 + mt * 16 + tr + 8];
            #pragma unroll
            for (int nt = 0; nt < 2; ++nt) {
                oacc[mt][nt][0] *= s0; oacc[mt][nt][1] *= s0;
                oacc[mt][nt][2] *= s1; oacc[mt][nt][3] *= s1;
            }
        }
        #pragma unroll
        for (int ks = 0; ks < 8; ++ks) {
            uint32_t af[4][4], bv[4];
            #pragma unroll
            for (int mt = 0; mt < 4; ++mt)
                ldsm_x4(af[mt], p_lm + (uint32_t)((mt * 16 * PS + ks * 16) * 2));
            ldsm_x4_t(bv, v_lm + (uint32_t)(ks * 16 * AS * 2));
            #pragma unroll
            for (int mt = 0; mt < 4; ++mt) {
                mma_f16(oacc[mt][0], af[mt], &bv[0]);
                mma_f16(oacc[mt][1], af[mt], &bv[2]);
            }
        }
    }

    __syncthreads();
    if (tid < 128) srow[tid] = 1.0f / l_run;
    __syncthreads();

    // epilogue -> fp16 o[token][h*64 + d]
    #pragma unroll
    for (int mt = 0; mt < 4; ++mt) {
        int r0 = warp_m * 64 + mt * 16 + tr;
        float i0 = srow[r0], i1 = srow[r0 + 8];
        size_t g0 = ((size_t)b * 1024 + q0 + r0) * C_DIM + h * DH
                    + warp_n * 16 + tc * 2;
        size_t g1 = g0 + (size_t)8 * C_DIM;
        #pragma unroll
        for (int nt = 0; nt < 2; ++nt) {
            *(__half2*)(o + g0 + nt * 8) =
                __floats2half2_rn(oacc[mt][nt][0] * i0, oacc[mt][nt][1] * i0);
            *(__half2*)(o + g1 + nt * 8) =
                __floats2half2_rn(oacc[mt][nt][2] * i1, oacc[mt][nt][3] * i1);
        }
    }
}

// ---------------------------------------------------------------------------
// Launch
// ---------------------------------------------------------------------------
extern "C" void kernel_launch(void* const* d_in, const int* in_sizes, int n_in,
                              void* d_out, int out_size)
{
    const float* x     = (const float*)d_in[0];
    const float* ln1_g = (const float*)d_in[1];
    const float* ln1_b = (const float*)d_in[2];
    const float* w_qkv = (const float*)d_in[3];
    const float* w_out = (const float*)d_in[4];
    const float* b_out = (const float*)d_in[5];
    const float* ln2_g = (const float*)d_in[6];
    const float* ln2_b = (const float*)d_in[7];
    const float* w1    = (const float*)d_in[8];
    const float* b1    = (const float*)d_in[9];
    const float* w2    = (const float*)d_in[10];
    const float* b2    = (const float*)d_in[11];
    float* out = (float*)d_out;

    __half *h, *qkv, *o, *mid, *wqkv_t, *wout_t, *w1_t, *w2_t;
    cudaGetSymbolAddress((void**)&h,      g_h);
    cudaGetSymbolAddress((void**)&qkv,    g_qkv);
    cudaGetSymbolAddress((void**)&o,      g_o);
    cudaGetSymbolAddress((void**)&mid,    g_mid);
    cudaGetSymbolAddress((void**)&wqkv_t, g_wqkv_t);
    cudaGetSymbolAddress((void**)&wout_t, g_wout_t);
    cudaGetSymbolAddress((void**)&w1_t,   g_w1_t);
    cudaGetSymbolAddress((void**)&w2_t,   g_w2_t);

    cudaFuncSetAttribute(attn_h_kernel,
                         cudaFuncAttributeMaxDynamicSharedMemorySize, ATT_SMEM_BYTES);
    cudaFuncSetAttribute((const void*)hgemm_kernel<false, 0>,
                         cudaFuncAttributeMaxDynamicSharedMemorySize, GEMM_SMEM_BYTES);
    cudaFuncSetAttribute((const void*)hgemm_kernel<false, 2>,
                         cudaFuncAttributeMaxDynamicSharedMemorySize, GEMM_SMEM_BYTES);
    cudaFuncSetAttribute((const void*)hgemm_kernel<true, 2>,
                         cudaFuncAttributeMaxDynamicSharedMemorySize, GEMM_SMEM_BYTES);

    dim3 tb(32, 8);
    // 0. Transpose weights to [N][K] fp16
    transpose_h_kernel<<<dim3(QKV_DIM / 32, C_DIM / 32), tb>>>(w_qkv, wqkv_t, C_DIM, QKV_DIM);
    transpose_h_kernel<<<dim3(C_DIM / 32, C_DIM / 32),   tb>>>(w_out, wout_t, C_DIM, C_DIM);
    transpose_h_kernel<<<dim3(MLP_DIM / 32, C_DIM / 32), tb>>>(w1, w1_t, C_DIM, MLP_DIM);
    transpose_h_kernel<<<dim3(C_DIM / 32, MLP_DIM / 32), tb>>>(w2, w2_t, MLP_DIM, C_DIM);

    // 1. h = fp16(LN1(x))
    ln_kernel<<<M_TOK, 256>>>(x, ln1_g, ln1_b, h);

    // 2. qkv = fp16(h @ w_qkv)
    hgemm_kernel<false, 2><<<dim3(QKV_DIM / 128, M_TOK / 128), 256, GEMM_SMEM_BYTES>>>(
        h, wqkv_t, nullptr, nullptr, qkv, M_TOK, QKV_DIM, C_DIM);

    // 3. o = fp16(attention(qkv))
    attn_h_kernel<<<dim3(8 * NHEAD, 1024 / 128), 256, ATT_SMEM_BYTES>>>(qkv, o);

    // 4. out = o @ w_out + b_out + x   (fp32)
    hgemm_kernel<false, 0><<<dim3(C_DIM / 128, M_TOK / 128), 256, GEMM_SMEM_BYTES>>>(
        o, wout_t, b_out, x, out, M_TOK, C_DIM, C_DIM);

    // 5. h = fp16(LN2(out))
    ln_kernel<<<M_TOK, 256>>>(out, ln2_g, ln2_b, h);

    // 6. mid = fp16(gelu(h @ w1 + b1))
    hgemm_kernel<true, 2><<<dim3(MLP_DIM / 128, M_TOK / 128), 256, GEMM_SMEM_BYTES>>>(
        h, w1_t, b1, nullptr, mid, M_TOK, MLP_DIM, C_DIM);

    // 7. out = out + mid @ w2 + b2   (fp32)
    hgemm_kernel<false, 0><<<dim3(C_DIM / 128, M_TOK / 128), 256, GEMM_SMEM_BYTES>>>(
        mid, w2_t, b2, out, out, M_TOK, C_DIM, MLP_DIM);
}